// round 3
// baseline (speedup 1.0000x reference)
#include <cuda_runtime.h>
#include <math.h>

#define BB 8
#define CC 192
#define HH 128
#define WW 128
#define HW 16384
#define NH 4
#define CH 48
#define C3 576
#define EPSN 1e-12f

// ---------------- scratch (device globals; no allocs) ----------------
__device__ float g_w3c[CC * CC * 9];                    // composed cn conv weights [o][i][t]
__device__ float g_cnf[(size_t)BB * CC * HW];           // cn_f                     (~100MB)
__device__ float g_mid[(size_t)BB * C3 * HW];           // qkv pre-depthwise        (~302MB)
__device__ float g_qkv[(size_t)BB * C3 * HW];           // qkv post-depthwise       (~302MB)
__device__ float g_ssq[BB * CC];                        // sum q^2 per (b,c)
__device__ float g_ssk[BB * CC];                        // sum k^2
__device__ float g_sscn[BB * CC];                       // sum cn_f^2
__device__ float g_dot[BB * CC];                        // sum q*cn_f
__device__ float g_S1[BB * NH * CH * CH];               // q @ k^T   (raw)
__device__ float g_S2[BB * NH * CH * CH];               // cn @ k^T  (raw)
__device__ float g_wcomb[BB * CC * CC];                 // Wp @ blockdiag(attn)

// ---------------- init: zero accumulators ----------------
__global__ void k_init() {
    int i = blockIdx.x * blockDim.x + threadIdx.x;
    if (i < BB * CC) { g_ssq[i] = 0.f; g_ssk[i] = 0.f; g_sscn[i] = 0.f; g_dot[i] = 0.f; }
    int n2 = BB * NH * CH * CH;
    for (int j = i; j < n2; j += gridDim.x * blockDim.x) { g_S1[j] = 0.f; g_S2[j] = 0.f; }
}

// ---------------- compose cn weights: W3c[o,i,t] = sum_m W3[o,m,t]*W1[m,i] ----------------
__global__ void k_compose(const float* __restrict__ w1, const float* __restrict__ w3) {
    int o = blockIdx.x / 9;
    int t = blockIdx.x % 9;
    int i = threadIdx.x;
    float acc = 0.f;
    for (int m = 0; m < CC; m++)
        acc = fmaf(w3[(o * CC + m) * 9 + t], w1[m * CC + i], acc);
    g_w3c[(o * CC + i) * 9 + t] = acc;
}

// ---------------- cn 3x3 conv (the big one) + sumsq(cn_f) ----------------
#define K2_OCB 16
#define K2_TY 16
#define K2_TX 64
#define K2_ICC 4

__global__ void __launch_bounds__(256) k_cn_conv(const float* __restrict__ cn) {
    __shared__ float sIn[K2_ICC][K2_TY + 2][K2_TX + 2];
    __shared__ float sW[K2_OCB][K2_ICC][9];

    int b   = blockIdx.z / 12;
    int oc0 = (blockIdx.z % 12) * K2_OCB;
    int y0  = blockIdx.y * K2_TY;
    int x0  = blockIdx.x * K2_TX;
    int tid = threadIdx.x;
    int py  = tid >> 4;           // 0..15
    int xb  = (tid & 15) << 2;    // 0,4,..,60

    float acc[K2_OCB][4];
#pragma unroll
    for (int o = 0; o < K2_OCB; o++)
#pragma unroll
        for (int p = 0; p < 4; p++) acc[o][p] = 0.f;

    for (int ic0 = 0; ic0 < CC; ic0 += K2_ICC) {
        // load input tile with halo (zero-padded)
        for (int idx = tid; idx < K2_ICC * (K2_TY + 2) * (K2_TX + 2); idx += 256) {
            int icl = idx / ((K2_TY + 2) * (K2_TX + 2));
            int rem = idx % ((K2_TY + 2) * (K2_TX + 2));
            int ry = rem / (K2_TX + 2), rx = rem % (K2_TX + 2);
            int y = y0 + ry - 1, x = x0 + rx - 1;
            float v = 0.f;
            if ((unsigned)y < HH && (unsigned)x < WW)
                v = cn[((size_t)(b * CC + ic0 + icl) * HH + y) * WW + x];
            sIn[icl][ry][rx] = v;
        }
        // load weights
        for (int idx = tid; idx < K2_OCB * K2_ICC * 9; idx += 256) {
            int o = idx / (K2_ICC * 9);
            int rem = idx % (K2_ICC * 9);
            sW[o][rem / 9][rem % 9] = g_w3c[((oc0 + o) * CC + ic0 + rem / 9) * 9 + rem % 9];
        }
        __syncthreads();

#pragma unroll
        for (int icl = 0; icl < K2_ICC; icl++) {
            float win[3][6];
#pragma unroll
            for (int ky = 0; ky < 3; ky++)
#pragma unroll
                for (int j = 0; j < 6; j++)
                    win[ky][j] = sIn[icl][py + ky][xb + j];
#pragma unroll
            for (int o = 0; o < K2_OCB; o++) {
#pragma unroll
                for (int ky = 0; ky < 3; ky++)
#pragma unroll
                    for (int kx = 0; kx < 3; kx++) {
                        float w = sW[o][icl][ky * 3 + kx];
#pragma unroll
                        for (int p = 0; p < 4; p++)
                            acc[o][p] = fmaf(w, win[ky][kx + p], acc[o][p]);
                    }
            }
        }
        __syncthreads();
    }

    int lane = tid & 31;
#pragma unroll
    for (int o = 0; o < K2_OCB; o++) {
        size_t base = ((size_t)(b * CC + oc0 + o) * HH + y0 + py) * WW + x0 + xb;
        float ss = 0.f;
#pragma unroll
        for (int p = 0; p < 4; p++) {
            g_cnf[base + p] = acc[o][p];
            ss = fmaf(acc[o][p], acc[o][p], ss);
        }
        for (int off = 16; off; off >>= 1) ss += __shfl_xor_sync(0xffffffffu, ss, off);
        if (lane == 0) atomicAdd(&g_sscn[b * CC + oc0 + o], ss);
    }
}

// ---------------- 1x1 conv GEMM: MODE 0 = qkv (x -> g_mid), MODE 1 = final (v -> out via Wcomb) ----------------
template <int MODE>
__global__ void __launch_bounds__(256) k_conv1x1(const float* __restrict__ Xin,
                                                 const float* __restrict__ Win,
                                                 float* __restrict__ Yout) {
    __shared__ __align__(16) float sX[16][256];
    __shared__ float sW[64][17];

    int b   = blockIdx.z;
    int oc0 = blockIdx.y * 64;
    int p0  = blockIdx.x * 256;
    int tid = threadIdx.x;
    int lane = tid & 31;
    int ocl  = (tid >> 5) * 8;   // 0,8,..,56
    int pxl  = lane * 8;         // 0..248

    const float* Xp = MODE ? g_qkv : Xin;
    int xChanBase   = MODE ? (b * C3 + 2 * CC) : (b * CC);   // v-part for MODE 1
    const float* Wp = MODE ? (g_wcomb + (size_t)b * CC * CC) : Win;
    float* Yp       = MODE ? Yout : g_mid;
    int yChanBase   = MODE ? (b * CC) : (b * C3);

    float acc[8][8];
#pragma unroll
    for (int o = 0; o < 8; o++)
#pragma unroll
        for (int j = 0; j < 8; j++) acc[o][j] = 0.f;

    for (int kc = 0; kc < CC; kc += 16) {
#pragma unroll
        for (int i = 0; i < 16; i++) {
            int idx = tid + i * 256;
            int r = idx >> 8, col = idx & 255;
            sX[r][col] = Xp[(size_t)(xChanBase + kc + r) * HW + p0 + col];
        }
#pragma unroll
        for (int i = 0; i < 4; i++) {
            int idx = tid + i * 256;
            int o = idx >> 4, kk = idx & 15;
            sW[o][kk] = Wp[(oc0 + o) * CC + kc + kk];
        }
        __syncthreads();
#pragma unroll
        for (int kk = 0; kk < 16; kk++) {
            float4 xa = *(const float4*)&sX[kk][pxl];
            float4 xb4 = *(const float4*)&sX[kk][pxl + 4];
            float xv[8] = {xa.x, xa.y, xa.z, xa.w, xb4.x, xb4.y, xb4.z, xb4.w};
#pragma unroll
            for (int o = 0; o < 8; o++) {
                float w = sW[ocl + o][kk];
#pragma unroll
                for (int j = 0; j < 8; j++)
                    acc[o][j] = fmaf(w, xv[j], acc[o][j]);
            }
        }
        __syncthreads();
    }
#pragma unroll
    for (int o = 0; o < 8; o++) {
        size_t base = (size_t)(yChanBase + oc0 + ocl + o) * HW + p0 + pxl;
#pragma unroll
        for (int j = 0; j < 8; j++) Yp[base + j] = acc[o][j];
    }
}

// ---------------- depthwise 3x3 (+ sumsq q/k, dot(q,cn_f)) ----------------
__global__ void __launch_bounds__(256) k_dw(const float* __restrict__ dww) {
    __shared__ float sT[10][130];
    int y0 = blockIdx.x * 8;
    int oc = blockIdx.y;
    int b  = blockIdx.z;
    int tid = threadIdx.x;

    const float* mid = g_mid + (size_t)(b * C3 + oc) * HW;
    for (int idx = tid; idx < 10 * 130; idx += 256) {
        int r = idx / 130, cc = idx % 130;
        int y = y0 + r - 1, x = cc - 1;
        sT[r][cc] = ((unsigned)y < HH && (unsigned)x < WW) ? mid[y * WW + x] : 0.f;
    }
    float dw[9];
#pragma unroll
    for (int t = 0; t < 9; t++) dw[t] = dww[oc * 9 + t];
    __syncthreads();

    int py = tid >> 5, lane = tid & 31, xb = lane * 4;
    float out4[4];
#pragma unroll
    for (int j = 0; j < 4; j++) {
        float v = 0.f;
#pragma unroll
        for (int ky = 0; ky < 3; ky++)
#pragma unroll
            for (int kx = 0; kx < 3; kx++)
                v = fmaf(dw[ky * 3 + kx], sT[py + ky][xb + j + kx], v);
        out4[j] = v;
    }
    size_t base = (size_t)(b * C3 + oc) * HW + (y0 + py) * WW + xb;
#pragma unroll
    for (int j = 0; j < 4; j++) g_qkv[base + j] = out4[j];

    if (oc < 2 * CC) {
        float ss = 0.f, dd = 0.f;
#pragma unroll
        for (int j = 0; j < 4; j++) ss = fmaf(out4[j], out4[j], ss);
        if (oc < CC) {
            const float* cf = g_cnf + (size_t)(b * CC + oc) * HW + (y0 + py) * WW + xb;
#pragma unroll
            for (int j = 0; j < 4; j++) dd = fmaf(out4[j], cf[j], dd);
        }
        for (int off = 16; off; off >>= 1) {
            ss += __shfl_xor_sync(0xffffffffu, ss, off);
            dd += __shfl_xor_sync(0xffffffffu, dd, off);
        }
        if (lane == 0) {
            if (oc < CC) { atomicAdd(&g_ssq[b * CC + oc], ss); atomicAdd(&g_dot[b * CC + oc], dd); }
            else         { atomicAdd(&g_ssk[b * CC + oc - CC], ss); }
        }
    }
}

// ---------------- attention GEMMs: S1 = q k^T, S2 = cn k^T (raw, pre-normalization) ----------------
__global__ void __launch_bounds__(256) k_attn_gemm() {
    __shared__ float sQ[48][33], sK[48][33], sC[48][33];
    int b = blockIdx.z, h = blockIdx.y;
    int s0 = blockIdx.x * 1024;
    int tid = threadIdx.x;
    int ti = tid >> 4, tj = tid & 15;

    float a1[3][3] = {}, a2[3][3] = {};
    const float* qb = g_qkv + (size_t)(b * C3 + h * CH) * HW;
    const float* kb = g_qkv + (size_t)(b * C3 + CC + h * CH) * HW;
    const float* cb = g_cnf + (size_t)(b * CC + h * CH) * HW;

    for (int st = 0; st < 1024; st += 32) {
#pragma unroll
        for (int i = 0; i < 6; i++) {
            int idx = tid + i * 256;
            int r = idx >> 5, ss = idx & 31;
            sQ[r][ss] = qb[(size_t)r * HW + s0 + st + ss];
            sK[r][ss] = kb[(size_t)r * HW + s0 + st + ss];
            sC[r][ss] = cb[(size_t)r * HW + s0 + st + ss];
        }
        __syncthreads();
#pragma unroll 4
        for (int ss = 0; ss < 32; ss++) {
            float qv[3], kv[3], cv[3];
#pragma unroll
            for (int i = 0; i < 3; i++) {
                qv[i] = sQ[ti * 3 + i][ss];
                cv[i] = sC[ti * 3 + i][ss];
                kv[i] = sK[tj * 3 + i][ss];
            }
#pragma unroll
            for (int i = 0; i < 3; i++)
#pragma unroll
                for (int j = 0; j < 3; j++) {
                    a1[i][j] = fmaf(qv[i], kv[j], a1[i][j]);
                    a2[i][j] = fmaf(cv[i], kv[j], a2[i][j]);
                }
        }
        __syncthreads();
    }
    int base = ((b * NH + h) * CH) * CH;
#pragma unroll
    for (int i = 0; i < 3; i++)
#pragma unroll
        for (int j = 0; j < 3; j++) {
            atomicAdd(&g_S1[base + (ti * 3 + i) * CH + tj * 3 + j], a1[i][j]);
            atomicAdd(&g_S2[base + (ti * 3 + i) * CH + tj * 3 + j], a2[i][j]);
        }
}

// ---------------- finalize: normalize, softmax, Wcomb = Wp @ blockdiag(attn) ----------------
__global__ void __launch_bounds__(256) k_finalize(const float* __restrict__ proj_w,
                                                  const float* __restrict__ temp) {
    __shared__ float L[CH * CH];
    __shared__ float rfA[CH], rfB[CH], cfc[CH];
    __shared__ float sWp[CC * CH];

    int h = blockIdx.x, b = blockIdx.y;
    int tid = threadIdx.x;

    if (tid < CH) {
        int gi = b * CC + h * CH + tid;
        float ssq = g_ssq[gi], sscn = g_sscn[gi], dt = g_dot[gi], ssk = g_ssk[gi];
        float a  = 1.f / fmaxf(sqrtf(ssq), EPSN);    // 1/||q||
        float bf = 1.f / fmaxf(sqrtf(sscn), EPSN);   // 1/||cn||
        float ssum = ssq * a * a + sscn * bf * bf + 2.f * dt * a * bf;  // ||qn+cnn||^2
        float inv_ns = 1.f / fmaxf(sqrtf(fmaxf(ssum, 0.f)), EPSN);
        rfA[tid] = a * inv_ns;
        rfB[tid] = bf * inv_ns;
        cfc[tid] = 1.f / fmaxf(sqrtf(ssk), EPSN);    // 1/||k||
    }
    __syncthreads();

    float tv = temp[h];
    int base = ((b * NH + h) * CH) * CH;
    for (int e = tid; e < CH * CH; e += 256) {
        int c = e / CH, d = e % CH;
        L[e] = (g_S1[base + e] * rfA[c] + g_S2[base + e] * rfB[c]) * cfc[d] * tv;
    }
    __syncthreads();

    // softmax over d: 8 warps x 6 rows
    int w = tid >> 5, lane = tid & 31;
    for (int k = 0; k < 6; k++) {
        int r = w * 6 + k;
        float v0 = L[r * CH + lane];
        float v1 = (lane < 16) ? L[r * CH + 32 + lane] : -1e30f;
        float m = fmaxf(v0, v1);
        for (int off = 16; off; off >>= 1) m = fmaxf(m, __shfl_xor_sync(0xffffffffu, m, off));
        float e0 = expf(v0 - m);
        float e1 = (lane < 16) ? expf(v1 - m) : 0.f;
        float s = e0 + e1;
        for (int off = 16; off; off >>= 1) s += __shfl_xor_sync(0xffffffffu, s, off);
        float inv = 1.f / s;
        L[r * CH + lane] = e0 * inv;
        if (lane < 16) L[r * CH + 32 + lane] = e1 * inv;
    }
    __syncthreads();

    // Wcomb[b][oc][h*48+d] = sum_c Wp[oc, h*48+c] * A[c][d]
    for (int idx = tid; idx < CC * CH; idx += 256)
        sWp[idx] = proj_w[(idx / CH) * CC + h * CH + (idx % CH)];
    __syncthreads();
    for (int e = tid; e < CC * CH; e += 256) {
        int oc = e / CH, d = e % CH;
        float s = 0.f;
#pragma unroll 8
        for (int c = 0; c < CH; c++)
            s = fmaf(sWp[oc * CH + c], L[c * CH + d], s);
        g_wcomb[(b * CC + oc) * CC + h * CH + d] = s;
    }
}

// ---------------- launch ----------------
extern "C" void kernel_launch(void* const* d_in, const int* in_sizes, int n_in,
                              void* d_out, int out_size) {
    const float* x    = (const float*)d_in[0];
    const float* cn   = (const float*)d_in[1];
    const float* w1   = (const float*)d_in[2];
    const float* w3   = (const float*)d_in[3];
    const float* qw   = (const float*)d_in[4];
    const float* dww  = (const float*)d_in[5];
    const float* pw   = (const float*)d_in[6];
    const float* temp = (const float*)d_in[7];
    float* out = (float*)d_out;

    k_init<<<288, 256>>>();
    k_compose<<<CC * 9, CC>>>(w1, w3);
    k_cn_conv<<<dim3(WW / K2_TX, HH / K2_TY, BB * 12), 256>>>(cn);
    k_conv1x1<0><<<dim3(HW / 256, C3 / 64, BB), 256>>>(x, qw, nullptr);
    k_dw<<<dim3(HH / 8, C3, BB), 256>>>(dww);
    k_attn_gemm<<<dim3(HW / 1024, NH, BB), 256>>>();
    k_finalize<<<dim3(NH, BB), 256>>>(pw, temp);
    k_conv1x1<1><<<dim3(HW / 256, CC / 64, BB), 256>>>(nullptr, nullptr, out);
}

// round 9
// speedup vs baseline: 2.8467x; 2.8467x over previous
#include <cuda_runtime.h>
#include <cuda_bf16.h>
#include <cstdint>
#include <math.h>

#define BB 8
#define CC 192
#define HH 128
#define WW 128
#define HW 16384
#define NH 4
#define CH 48
#define C3 576
#define EPSN 1e-12f
#define PADW 130
#define PADSZ (PADW * PADW)   // 16900

// ---------------- scratch (device globals; no allocs) ----------------
__device__ __align__(16) float g_cnpad[(size_t)BB * CC * PADSZ];
__device__ __align__(16) float g_cnf[(size_t)BB * CC * HW];
__device__ __align__(16) float g_mid[(size_t)BB * C3 * HW];
__device__ __align__(16) float g_qkv[(size_t)BB * C3 * HW];
__device__ float g_ssq[BB * CC];
__device__ float g_ssk[BB * CC];
__device__ float g_sscn[BB * CC];
__device__ float g_dot[BB * CC];
__device__ float g_S1[BB * NH * CH * CH];
__device__ float g_S2[BB * NH * CH * CH];
__device__ __align__(16) __nv_bfloat16 g_w3t_h[9 * CC * CC];   // [tap][oc][ic]
__device__ __align__(16) __nv_bfloat16 g_w3t_l[9 * CC * CC];
__device__ __align__(16) __nv_bfloat16 g_wq_h[C3 * CC];        // [oc][ic]
__device__ __align__(16) __nv_bfloat16 g_wq_l[C3 * CC];
__device__ __align__(16) __nv_bfloat16 g_wcb_h[BB * CC * CC];  // [b][oc][cin]
__device__ __align__(16) __nv_bfloat16 g_wcb_l[BB * CC * CC];

// ---------------- helpers ----------------
__device__ __forceinline__ uint32_t smem_to_u32(const void* p) {
    uint32_t a;
    asm("{ .reg .u64 t; cvta.to.shared.u64 t, %1; cvt.u32.u64 %0, t; }" : "=r"(a) : "l"(p));
    return a;
}
__device__ __forceinline__ void ldsm4(uint32_t* r, uint32_t addr) {
    asm volatile("ldmatrix.sync.aligned.m8n8.x4.shared.b16 {%0,%1,%2,%3}, [%4];"
                 : "=r"(r[0]), "=r"(r[1]), "=r"(r[2]), "=r"(r[3]) : "r"(addr));
}
__device__ __forceinline__ void mma16816(float* d, const uint32_t* a, uint32_t b0, uint32_t b1) {
    asm volatile(
        "mma.sync.aligned.m16n8k16.row.col.f32.bf16.bf16.f32 "
        "{%0,%1,%2,%3}, {%4,%5,%6,%7}, {%8,%9}, {%0,%1,%2,%3};"
        : "+f"(d[0]), "+f"(d[1]), "+f"(d[2]), "+f"(d[3])
        : "r"(a[0]), "r"(a[1]), "r"(a[2]), "r"(a[3]), "r"(b0), "r"(b1));
}
__device__ __forceinline__ uint32_t pack_bf2(__nv_bfloat16 a, __nv_bfloat16 b) {
    __nv_bfloat162 v = __halves2bfloat162(a, b);
    return *(uint32_t*)&v;
}

// ---------------- init ----------------
__global__ void k_init() {
    int i = blockIdx.x * blockDim.x + threadIdx.x;
    if (i < BB * CC) { g_ssq[i] = 0.f; g_ssk[i] = 0.f; g_sscn[i] = 0.f; g_dot[i] = 0.f; }
    int n2 = BB * NH * CH * CH;
    for (int j = i; j < n2; j += gridDim.x * blockDim.x) { g_S1[j] = 0.f; g_S2[j] = 0.f; }
}

// ---------------- pad cn into 130x130 zero-bordered planes ----------------
__global__ void k_pad(const float* __restrict__ cn) {
    size_t idx = (size_t)blockIdx.x * blockDim.x + threadIdx.x;
    size_t total = (size_t)BB * CC * PADSZ;
    if (idx >= total) return;
    int bc = (int)(idx / PADSZ);
    int rem = (int)(idx % PADSZ);
    int yy = rem / PADW, xx = rem % PADW;
    float v = 0.f;
    if (yy >= 1 && yy <= HH && xx >= 1 && xx <= WW)
        v = cn[(size_t)bc * HW + (yy - 1) * WW + (xx - 1)];
    g_cnpad[idx] = v;
}

// ---------------- compose cn weights -> bf16 hi/lo [tap][oc][ic] ----------------
__global__ void k_compose(const float* __restrict__ w1, const float* __restrict__ w3) {
    int o = blockIdx.x / 9;
    int t = blockIdx.x % 9;
    int i = threadIdx.x;
    float acc = 0.f;
    for (int m = 0; m < CC; m++)
        acc = fmaf(w3[(o * CC + m) * 9 + t], w1[m * CC + i], acc);
    __nv_bfloat16 h = __float2bfloat16(acc);
    __nv_bfloat16 l = __float2bfloat16(acc - __bfloat162float(h));
    size_t e = ((size_t)t * CC + o) * CC + i;
    g_w3t_h[e] = h; g_w3t_l[e] = l;
}

// ---------------- qkv weight prep ----------------
__global__ void k_wprep(const float* __restrict__ qw) {
    int i = blockIdx.x * blockDim.x + threadIdx.x;
    if (i >= C3 * CC) return;
    float v = qw[i];
    __nv_bfloat16 h = __float2bfloat16(v);
    g_wq_h[i] = h;
    g_wq_l[i] = __float2bfloat16(v - __bfloat162float(h));
}

// ---------------- warp-MMA split-bf16 GEMM ----------------
// Tile: M=128 pixels x N=192 oc, K chunks of 64. 8 warps: 4(m) x 2(n), warp tile 32x96.
// MODE 0: qkv 1x1 (A=x, B=g_wq, Out=g_mid, grid.y=3 oc-groups)
// MODE 1: final   (A=v, B=g_wcb, Out=d_out)
// MODE 2: cn conv (A=cnpad shifted, B=g_w3t, Out=g_cnf, 27 chunks = 9 taps x 3 kc)
#define AP 144                      // bytes per A smem row (64 bf16 + 8 pad)
#define OFF_AH 0
#define OFF_AL 18432
#define OFF_BH 36864
#define OFF_BL 64512
#define SMEM_G 92160

template <int MODE>
__global__ void __launch_bounds__(256, 1) k_gemm(const float* __restrict__ Ain,
                                                 float* __restrict__ OutExt) {
    extern __shared__ __align__(16) char smem[];
    uint32_t sb = smem_to_u32(smem);
    int tid = threadIdx.x, wid = tid >> 5, lane = tid & 31;
    int b = blockIdx.z, tile = blockIdx.x, grp = blockIdx.y;
    const int NC = (MODE == 2) ? 27 : 3;
    int p0 = tile * 128;
    int mw = wid & 3, nw = wid >> 2;
    int mbase = mw * 32, nbase = nw * 96;

    float acc[2][12][4];
#pragma unroll
    for (int fm = 0; fm < 2; fm++)
#pragma unroll
        for (int f = 0; f < 12; f++)
#pragma unroll
            for (int r = 0; r < 4; r++) acc[fm][f][r] = 0.f;

#pragma unroll 1
    for (int c = 0; c < NC; ++c) {
        int kc, t9 = 0, dy = 0, dx = 0;
        if (MODE == 2) { t9 = c / 3; kc = c - t9 * 3; dy = t9 / 3 - 1; dx = t9 % 3 - 1; }
        else kc = c;

        // ---- A tile: [m=128][k=64] bf16 hi/lo, gmem fp32 -> split ----
        {
            int m = tid & 127, g = tid >> 7;
            const float* a0;
            size_t rstride;
            if (MODE == 2) {
                a0 = g_cnpad + (size_t)(b * CC + kc * 64) * PADSZ
                   + (size_t)(tile + 1 + dy) * PADW + (1 + dx) + m;
                rstride = PADSZ;
            } else {
                int chb = (MODE == 0) ? b * CC : (b * C3 + 2 * CC);
                const float* src = (MODE == 0) ? Ain : g_qkv;
                a0 = src + (size_t)(chb + kc * 64) * HW + p0 + m;
                rstride = HW;
            }
            char* aH = smem + OFF_AH;
            char* aL = smem + OFF_AL;
#pragma unroll
            for (int i = 0; i < 16; i++) {
                int k0 = g * 32 + i * 2;
                float v0 = a0[(size_t)k0 * rstride];
                float v1 = a0[(size_t)(k0 + 1) * rstride];
                __nv_bfloat16 h0 = __float2bfloat16(v0), h1 = __float2bfloat16(v1);
                __nv_bfloat16 l0 = __float2bfloat16(v0 - __bfloat162float(h0));
                __nv_bfloat16 l1 = __float2bfloat16(v1 - __bfloat162float(h1));
                uint32_t off = (uint32_t)(m * AP + k0 * 2);
                *(uint32_t*)(aH + off) = pack_bf2(h0, h1);
                *(uint32_t*)(aL + off) = pack_bf2(l0, l1);
            }
        }
        // ---- B tile: [n=192][k=64] preconverted bf16 hi/lo ----
        {
            const __nv_bfloat16 *bhp, *blp;
            size_t row0;
            if (MODE == 2)      { bhp = g_w3t_h; blp = g_w3t_l; row0 = (size_t)t9 * CC; }
            else if (MODE == 0) { bhp = g_wq_h;  blp = g_wq_l;  row0 = (size_t)grp * CC; }
            else                { bhp = g_wcb_h; blp = g_wcb_l; row0 = (size_t)b * CC; }
#pragma unroll
            for (int i = 0; i < 6; i++) {
                int idx = tid + i * 256;
                int r = idx >> 3, gg = idx & 7;
                size_t e = (row0 + r) * CC + kc * 64 + gg * 8;
                *(uint4*)(smem + OFF_BH + r * AP + gg * 16) = *(const uint4*)(bhp + e);
                *(uint4*)(smem + OFF_BL + r * AP + gg * 16) = *(const uint4*)(blp + e);
            }
        }
        __syncthreads();

        // ---- compute: 4 k16 steps ----
#pragma unroll
        for (int kk = 0; kk < 64; kk += 16) {
            uint32_t afh[2][4], afl[2][4];
#pragma unroll
            for (int fm = 0; fm < 2; fm++) {
                uint32_t rowb = (uint32_t)((mbase + fm * 16 + (lane & 15)) * AP
                               + (kk + ((lane >> 4) << 3)) * 2);
                ldsm4(afh[fm], sb + OFF_AH + rowb);
                ldsm4(afl[fm], sb + OFF_AL + rowb);
            }
#pragma unroll
            for (int fn2 = 0; fn2 < 6; fn2++) {
                uint32_t bh4[4], bl4[4];
                uint32_t rowb = (uint32_t)((nbase + fn2 * 16 + (lane & 7) + ((lane >> 4) << 3)) * AP
                               + (kk + (((lane >> 3) & 1) << 3)) * 2);
                ldsm4(bh4, sb + OFF_BH + rowb);
                ldsm4(bl4, sb + OFF_BL + rowb);
#pragma unroll
                for (int fm = 0; fm < 2; fm++) {
#pragma unroll
                    for (int s2 = 0; s2 < 2; s2++) {
                        float* d = acc[fm][fn2 * 2 + s2];
                        mma16816(d, afh[fm], bh4[s2 * 2], bh4[s2 * 2 + 1]);
                        mma16816(d, afh[fm], bl4[s2 * 2], bl4[s2 * 2 + 1]);
                        mma16816(d, afl[fm], bh4[s2 * 2], bh4[s2 * 2 + 1]);
                    }
                }
            }
        }
        __syncthreads();
    }

    // ---- epilogue: stage halves of 96 oc through smem for coalesced stores ----
    float* Outp;
    size_t ocb;
    if (MODE == 0)      { Outp = g_mid;  ocb = (size_t)b * C3 + grp * CC; }
    else if (MODE == 1) { Outp = OutExt; ocb = (size_t)b * CC; }
    else                { Outp = g_cnf;  ocb = (size_t)b * CC; }
    float* stg = (float*)smem;
#pragma unroll
    for (int h = 0; h < 2; h++) {
        if (nw == h) {
#pragma unroll
            for (int fm = 0; fm < 2; fm++)
#pragma unroll
                for (int f = 0; f < 12; f++) {
                    int nl = f * 8 + 2 * (lane & 3);
                    int mr = mbase + fm * 16 + (lane >> 2);
                    float* a = acc[fm][f];
                    stg[nl * 132 + mr]           = a[0];
                    stg[(nl + 1) * 132 + mr]     = a[1];
                    stg[nl * 132 + mr + 8]       = a[2];
                    stg[(nl + 1) * 132 + mr + 8] = a[3];
                }
        }
        __syncthreads();
#pragma unroll
        for (int r = 0; r < 48; r++) {
            int flat = tid + r * 256;
            int mm = flat & 127, nn = flat >> 7;
            Outp[(ocb + h * 96 + nn) * (size_t)HW + p0 + mm] = stg[nn * 132 + mm];
        }
        __syncthreads();
    }
}

// ---------------- depthwise 3x3 (+ sumsq q/k/cn, dot(q,cn_f)) ----------------
__global__ void __launch_bounds__(256) k_dw(const float* __restrict__ dww) {
    __shared__ float sT[10][130];
    int y0 = blockIdx.x * 8;
    int oc = blockIdx.y;
    int b  = blockIdx.z;
    int tid = threadIdx.x;

    const float* mid = g_mid + (size_t)(b * C3 + oc) * HW;
    for (int idx = tid; idx < 10 * 130; idx += 256) {
        int r = idx / 130, cc = idx % 130;
        int y = y0 + r - 1, x = cc - 1;
        sT[r][cc] = ((unsigned)y < HH && (unsigned)x < WW) ? mid[y * WW + x] : 0.f;
    }
    float dw[9];
#pragma unroll
    for (int t = 0; t < 9; t++) dw[t] = dww[oc * 9 + t];
    __syncthreads();

    int py = tid >> 5, lane = tid & 31, xb = lane * 4;
    float out4[4];
#pragma unroll
    for (int j = 0; j < 4; j++) {
        float v = 0.f;
#pragma unroll
        for (int ky = 0; ky < 3; ky++)
#pragma unroll
            for (int kx = 0; kx < 3; kx++)
                v = fmaf(dw[ky * 3 + kx], sT[py + ky][xb + j + kx], v);
        out4[j] = v;
    }
    size_t base = (size_t)(b * C3 + oc) * HW + (y0 + py) * WW + xb;
#pragma unroll
    for (int j = 0; j < 4; j++) g_qkv[base + j] = out4[j];

    if (oc < 2 * CC) {
        float ss = 0.f, dd = 0.f, sc = 0.f;
#pragma unroll
        for (int j = 0; j < 4; j++) ss = fmaf(out4[j], out4[j], ss);
        if (oc < CC) {
            const float* cf = g_cnf + (size_t)(b * CC + oc) * HW + (y0 + py) * WW + xb;
#pragma unroll
            for (int j = 0; j < 4; j++) {
                float cv = cf[j];
                dd = fmaf(out4[j], cv, dd);
                sc = fmaf(cv, cv, sc);
            }
        }
        for (int off = 16; off; off >>= 1) {
            ss += __shfl_xor_sync(0xffffffffu, ss, off);
            dd += __shfl_xor_sync(0xffffffffu, dd, off);
            sc += __shfl_xor_sync(0xffffffffu, sc, off);
        }
        if (lane == 0) {
            if (oc < CC) {
                atomicAdd(&g_ssq[b * CC + oc], ss);
                atomicAdd(&g_dot[b * CC + oc], dd);
                atomicAdd(&g_sscn[b * CC + oc], sc);
            } else {
                atomicAdd(&g_ssk[b * CC + oc - CC], ss);
            }
        }
    }
}

// ---------------- attention GEMMs: S1 = q k^T, S2 = cn k^T ----------------
__global__ void __launch_bounds__(256) k_attn_gemm() {
    __shared__ float sQ[48][33], sK[48][33], sC[48][33];
    int b = blockIdx.z, h = blockIdx.y;
    int s0 = blockIdx.x * 1024;
    int tid = threadIdx.x;
    int ti = tid >> 4, tj = tid & 15;

    float a1[3][3] = {}, a2[3][3] = {};
    const float* qb = g_qkv + (size_t)(b * C3 + h * CH) * HW;
    const float* kb = g_qkv + (size_t)(b * C3 + CC + h * CH) * HW;
    const float* cb = g_cnf + (size_t)(b * CC + h * CH) * HW;

    for (int st = 0; st < 1024; st += 32) {
#pragma unroll
        for (int i = 0; i < 6; i++) {
            int idx = tid + i * 256;
            int r = idx >> 5, ss = idx & 31;
            sQ[r][ss] = qb[(size_t)r * HW + s0 + st + ss];
            sK[r][ss] = kb[(size_t)r * HW + s0 + st + ss];
            sC[r][ss] = cb[(size_t)r * HW + s0 + st + ss];
        }
        __syncthreads();
#pragma unroll 4
        for (int ss = 0; ss < 32; ss++) {
            float qv[3], kv[3], cv[3];
#pragma unroll
            for (int i = 0; i < 3; i++) {
                qv[i] = sQ[ti * 3 + i][ss];
                cv[i] = sC[ti * 3 + i][ss];
                kv[i] = sK[tj * 3 + i][ss];
            }
#pragma unroll
            for (int i = 0; i < 3; i++)
#pragma unroll
                for (int j = 0; j < 3; j++) {
                    a1[i][j] = fmaf(qv[i], kv[j], a1[i][j]);
                    a2[i][j] = fmaf(cv[i], kv[j], a2[i][j]);
                }
        }
        __syncthreads();
    }
    int base = ((b * NH + h) * CH) * CH;
#pragma unroll
    for (int i = 0; i < 3; i++)
#pragma unroll
        for (int j = 0; j < 3; j++) {
            atomicAdd(&g_S1[base + (ti * 3 + i) * CH + tj * 3 + j], a1[i][j]);
            atomicAdd(&g_S2[base + (ti * 3 + i) * CH + tj * 3 + j], a2[i][j]);
        }
}

// ---------------- finalize: normalize, softmax, Wcomb(hi/lo bf16) ----------------
__global__ void __launch_bounds__(256) k_finalize(const float* __restrict__ proj_w,
                                                  const float* __restrict__ temp) {
    __shared__ float L[CH * CH];
    __shared__ float rfA[CH], rfB[CH], cfc[CH];
    __shared__ float sWp[CC * CH];

    int h = blockIdx.x, b = blockIdx.y;
    int tid = threadIdx.x;

    if (tid < CH) {
        int gi = b * CC + h * CH + tid;
        float ssq = g_ssq[gi], sscn = g_sscn[gi], dt = g_dot[gi], ssk = g_ssk[gi];
        float a  = 1.f / fmaxf(sqrtf(ssq), EPSN);
        float bf = 1.f / fmaxf(sqrtf(sscn), EPSN);
        float ssum = ssq * a * a + sscn * bf * bf + 2.f * dt * a * bf;
        float inv_ns = 1.f / fmaxf(sqrtf(fmaxf(ssum, 0.f)), EPSN);
        rfA[tid] = a * inv_ns;
        rfB[tid] = bf * inv_ns;
        cfc[tid] = 1.f / fmaxf(sqrtf(ssk), EPSN);
    }
    __syncthreads();

    float tv = temp[h];
    int base = ((b * NH + h) * CH) * CH;
    for (int e = tid; e < CH * CH; e += 256) {
        int c = e / CH, d = e % CH;
        L[e] = (g_S1[base + e] * rfA[c] + g_S2[base + e] * rfB[c]) * cfc[d] * tv;
    }
    __syncthreads();

    int w = tid >> 5, lane = tid & 31;
    for (int k = 0; k < 6; k++) {
        int r = w * 6 + k;
        float v0 = L[r * CH + lane];
        float v1 = (lane < 16) ? L[r * CH + 32 + lane] : -1e30f;
        float m = fmaxf(v0, v1);
        for (int off = 16; off; off >>= 1) m = fmaxf(m, __shfl_xor_sync(0xffffffffu, m, off));
        float e0 = expf(v0 - m);
        float e1 = (lane < 16) ? expf(v1 - m) : 0.f;
        float s = e0 + e1;
        for (int off = 16; off; off >>= 1) s += __shfl_xor_sync(0xffffffffu, s, off);
        float inv = 1.f / s;
        L[r * CH + lane] = e0 * inv;
        if (lane < 16) L[r * CH + 32 + lane] = e1 * inv;
    }
    __syncthreads();

    for (int idx = tid; idx < CC * CH; idx += 256)
        sWp[idx] = proj_w[(idx / CH) * CC + h * CH + (idx % CH)];
    __syncthreads();
    for (int e = tid; e < CC * CH; e += 256) {
        int oc = e / CH, d = e % CH;
        float s = 0.f;
#pragma unroll 8
        for (int c = 0; c < CH; c++)
            s = fmaf(sWp[oc * CH + c], L[c * CH + d], s);
        size_t oe = ((size_t)b * CC + oc) * CC + h * CH + d;
        __nv_bfloat16 hv = __float2bfloat16(s);
        g_wcb_h[oe] = hv;
        g_wcb_l[oe] = __float2bfloat16(s - __bfloat162float(hv));
    }
}

// ---------------- launch ----------------
extern "C" void kernel_launch(void* const* d_in, const int* in_sizes, int n_in,
                              void* d_out, int out_size) {
    const float* x    = (const float*)d_in[0];
    const float* cn   = (const float*)d_in[1];
    const float* w1   = (const float*)d_in[2];
    const float* w3   = (const float*)d_in[3];
    const float* qw   = (const float*)d_in[4];
    const float* dww  = (const float*)d_in[5];
    const float* pw   = (const float*)d_in[6];
    const float* temp = (const float*)d_in[7];
    float* out = (float*)d_out;

    cudaFuncSetAttribute(k_gemm<0>, cudaFuncAttributeMaxDynamicSharedMemorySize, SMEM_G);
    cudaFuncSetAttribute(k_gemm<1>, cudaFuncAttributeMaxDynamicSharedMemorySize, SMEM_G);
    cudaFuncSetAttribute(k_gemm<2>, cudaFuncAttributeMaxDynamicSharedMemorySize, SMEM_G);

    k_init<<<288, 256>>>();
    k_compose<<<CC * 9, CC>>>(w1, w3);
    k_wprep<<<(C3 * CC + 255) / 256, 256>>>(qw);
    {
        size_t total = (size_t)BB * CC * PADSZ;
        k_pad<<<(unsigned)((total + 255) / 256), 256>>>(cn);
    }
    k_gemm<2><<<dim3(128, 1, BB), 256, SMEM_G>>>(nullptr, nullptr);   // cn conv3x3
    k_gemm<0><<<dim3(128, 3, BB), 256, SMEM_G>>>(x, nullptr);         // qkv 1x1
    k_dw<<<dim3(HH / 8, C3, BB), 256>>>(dww);
    k_attn_gemm<<<dim3(HW / 1024, NH, BB), 256>>>();
    k_finalize<<<dim3(NH, BB), 256>>>(pw, temp);
    k_gemm<1><<<dim3(128, 1, BB), 256, SMEM_G>>>(nullptr, out);       // Wcomb @ v
}

// round 12
// speedup vs baseline: 2.9960x; 1.0524x over previous
#include <cuda_runtime.h>
#include <cuda_bf16.h>
#include <cstdint>
#include <math.h>

#define BB 8
#define CC 192
#define HH 128
#define WW 128
#define HW 16384
#define NH 4
#define CH 48
#define C3 576
#define EPSN 1e-12f

// ---------------- scratch (device globals; no allocs) ----------------
__device__ __align__(16) float g_cnf[(size_t)BB * CC * HW];
__device__ __align__(16) float g_mid[(size_t)BB * C3 * HW];
__device__ __align__(16) float g_qkv[(size_t)BB * C3 * HW];
__device__ float g_ssq[BB * CC];
__device__ float g_ssk[BB * CC];
__device__ float g_sscn[BB * CC];
__device__ float g_dot[BB * CC];
__device__ float g_S1[BB * NH * CH * CH];
__device__ float g_S2[BB * NH * CH * CH];
__device__ __align__(16) __nv_bfloat16 g_w3t_h[9 * CC * CC];   // [tap][oc][ic]
__device__ __align__(16) __nv_bfloat16 g_w3t_l[9 * CC * CC];
__device__ __align__(16) __nv_bfloat16 g_wq_h[C3 * CC];        // [oc][ic]
__device__ __align__(16) __nv_bfloat16 g_wq_l[C3 * CC];
__device__ __align__(16) __nv_bfloat16 g_wcb_h[BB * CC * CC];  // [b][oc][cin]
__device__ __align__(16) __nv_bfloat16 g_wcb_l[BB * CC * CC];

// ---------------- helpers ----------------
__device__ __forceinline__ uint32_t smem_to_u32(const void* p) {
    uint32_t a;
    asm("{ .reg .u64 t; cvta.to.shared.u64 t, %1; cvt.u32.u64 %0, t; }" : "=r"(a) : "l"(p));
    return a;
}
__device__ __forceinline__ void ldsm4(uint32_t* r, uint32_t addr) {
    asm volatile("ldmatrix.sync.aligned.m8n8.x4.shared.b16 {%0,%1,%2,%3}, [%4];"
                 : "=r"(r[0]), "=r"(r[1]), "=r"(r[2]), "=r"(r[3]) : "r"(addr));
}
__device__ __forceinline__ void mma16816(float* d, const uint32_t* a, uint32_t b0, uint32_t b1) {
    asm volatile(
        "mma.sync.aligned.m16n8k16.row.col.f32.bf16.bf16.f32 "
        "{%0,%1,%2,%3}, {%4,%5,%6,%7}, {%8,%9}, {%0,%1,%2,%3};"
        : "+f"(d[0]), "+f"(d[1]), "+f"(d[2]), "+f"(d[3])
        : "r"(a[0]), "r"(a[1]), "r"(a[2]), "r"(a[3]), "r"(b0), "r"(b1));
}
__device__ __forceinline__ uint32_t pack_bf2(__nv_bfloat16 a, __nv_bfloat16 b) {
    __nv_bfloat162 v = __halves2bfloat162(a, b);
    return *(uint32_t*)&v;
}
__device__ __forceinline__ void split_pair(float v0, float v1, uint32_t& hi, uint32_t& lo) {
    __nv_bfloat16 h0 = __float2bfloat16(v0), h1 = __float2bfloat16(v1);
    __nv_bfloat16 l0 = __float2bfloat16(v0 - __bfloat162float(h0));
    __nv_bfloat16 l1 = __float2bfloat16(v1 - __bfloat162float(h1));
    hi = pack_bf2(h0, h1);
    lo = pack_bf2(l0, l1);
}

#define AP 144      // B/A row pitch for 64-k tiles (128B data + 16 pad)
#define APK 400     // A row pitch for full K=192 (384B data + 16 pad)

// B tile loader: [192 rows][64 k] -> smem pitch AP
__device__ __forceinline__ void load_b_tile(const __nv_bfloat16* __restrict__ bhp,
                                            const __nv_bfloat16* __restrict__ blp,
                                            size_t row0, int koff, char* smem,
                                            uint32_t offBH, uint32_t offBL, int tid) {
#pragma unroll
    for (int i = 0; i < 6; i++) {
        int idx = tid + i * 256;
        int r = idx >> 3, gg = idx & 7;
        size_t e = (row0 + r) * CC + koff + gg * 8;
        *(uint4*)(smem + offBH + r * AP + gg * 16) = *(const uint4*)(bhp + e);
        *(uint4*)(smem + offBL + r * AP + gg * 16) = *(const uint4*)(blp + e);
    }
}

// MMA over one 64-k chunk. aBaseH/aBaseL include view & column base offsets; row stride = astride.
__device__ __forceinline__ void mma_chunk(uint32_t sb, uint32_t aBaseH, uint32_t aBaseL,
                                          uint32_t astride, uint32_t offBH, uint32_t offBL,
                                          int lane, int mbase, int nbase, float acc[2][12][4]) {
#pragma unroll
    for (int kk = 0; kk < 64; kk += 16) {
        uint32_t afh[2][4], afl[2][4];
#pragma unroll
        for (int fm = 0; fm < 2; fm++) {
            uint32_t rel = (uint32_t)((mbase + fm * 16 + (lane & 15)) * astride
                         + (kk + ((lane >> 4) << 3)) * 2);
            ldsm4(afh[fm], sb + aBaseH + rel);
            ldsm4(afl[fm], sb + aBaseL + rel);
        }
#pragma unroll
        for (int fn2 = 0; fn2 < 6; fn2++) {
            uint32_t bh4[4], bl4[4];
            uint32_t rowb = (uint32_t)((nbase + fn2 * 16 + (lane & 7) + ((lane >> 4) << 3)) * AP
                           + (kk + (((lane >> 3) & 1) << 3)) * 2);
            ldsm4(bh4, sb + offBH + rowb);
            ldsm4(bl4, sb + offBL + rowb);
#pragma unroll
            for (int fm = 0; fm < 2; fm++) {
#pragma unroll
                for (int s2 = 0; s2 < 2; s2++) {
                    float* d = acc[fm][fn2 * 2 + s2];
                    mma16816(d, afh[fm], bh4[s2 * 2], bh4[s2 * 2 + 1]);
                    mma16816(d, afh[fm], bl4[s2 * 2], bl4[s2 * 2 + 1]);
                    mma16816(d, afl[fm], bh4[s2 * 2], bh4[s2 * 2 + 1]);
                }
            }
        }
    }
}

// epilogue: transpose-stage through smem, coalesced channel-major stores
__device__ __forceinline__ void epilogue_store(float acc[2][12][4], char* smem, uint32_t stgOff,
                                               float* __restrict__ Outp, size_t ocb, int p0,
                                               int tid, int wid, int lane) {
    float* stg = (float*)(smem + stgOff);
    int mw = wid & 3, nw = wid >> 2;
    int mbase = mw * 32;
#pragma unroll
    for (int h = 0; h < 2; h++) {
        if (nw == h) {
#pragma unroll
            for (int fm = 0; fm < 2; fm++)
#pragma unroll
                for (int f = 0; f < 12; f++) {
                    int nl = f * 8 + 2 * (lane & 3);
                    int mr = mbase + fm * 16 + (lane >> 2);
                    float* a = acc[fm][f];
                    stg[nl * 132 + mr]           = a[0];
                    stg[(nl + 1) * 132 + mr]     = a[1];
                    stg[nl * 132 + mr + 8]       = a[2];
                    stg[(nl + 1) * 132 + mr + 8] = a[3];
                }
        }
        __syncthreads();
#pragma unroll
        for (int r = 0; r < 48; r++) {
            int flat = tid + r * 256;
            int mm = flat & 127, nn = flat >> 7;
            Outp[(ocb + h * 96 + nn) * (size_t)HW + p0 + mm] = stg[nn * 132 + mm];
        }
        __syncthreads();
    }
}

// ---------------- init ----------------
__global__ void k_init() {
    int i = blockIdx.x * blockDim.x + threadIdx.x;
    if (i < BB * CC) { g_ssq[i] = 0.f; g_ssk[i] = 0.f; g_sscn[i] = 0.f; g_dot[i] = 0.f; }
    int n2 = BB * NH * CH * CH;
    for (int j = i; j < n2; j += gridDim.x * blockDim.x) { g_S1[j] = 0.f; g_S2[j] = 0.f; }
}

// ---------------- compose cn weights -> bf16 hi/lo [tap][oc][ic] ----------------
__global__ void k_compose(const float* __restrict__ w1, const float* __restrict__ w3) {
    int o = blockIdx.x / 9;
    int t = blockIdx.x % 9;
    int i = threadIdx.x;
    float acc = 0.f;
    for (int m = 0; m < CC; m++)
        acc = fmaf(w3[(o * CC + m) * 9 + t], w1[m * CC + i], acc);
    __nv_bfloat16 h = __float2bfloat16(acc);
    __nv_bfloat16 l = __float2bfloat16(acc - __bfloat162float(h));
    size_t e = ((size_t)t * CC + o) * CC + i;
    g_w3t_h[e] = h; g_w3t_l[e] = l;
}

// ---------------- qkv weight prep ----------------
__global__ void k_wprep(const float* __restrict__ qw) {
    int i = blockIdx.x * blockDim.x + threadIdx.x;
    if (i >= C3 * CC) return;
    float v = qw[i];
    __nv_bfloat16 h = __float2bfloat16(v);
    g_wq_h[i] = h;
    g_wq_l[i] = __float2bfloat16(v - __bfloat162float(h));
}

// ================= cn conv 3x3 GEMM =================
// A slab per k-chunk: 3 y-rows x 130 px x 64 k (hi/lo), 9 taps read shifted views.
#define CN_AH 0u
#define CN_PL (3 * 130 * AP)          // 56160 per plane
#define CN_AL CN_PL
#define CN_BH (2 * CN_PL)             // 112320
#define CN_BL (CN_BH + 192 * AP)      // 139968
#define CN_SMEM (CN_BL + 192 * AP)    // 167616

__global__ void __launch_bounds__(256, 1) k_gemm_cn(const float* __restrict__ cn) {
    extern __shared__ __align__(16) char smem[];
    uint32_t sb = smem_to_u32(smem);
    int tid = threadIdx.x, wid = tid >> 5, lane = tid & 31;
    int b = blockIdx.z, tile = blockIdx.x;
    int mbase = (wid & 3) * 32, nbase = (wid >> 2) * 96;

    float acc[2][12][4];
#pragma unroll
    for (int fm = 0; fm < 2; fm++)
#pragma unroll
        for (int f = 0; f < 12; f++)
#pragma unroll
            for (int r = 0; r < 4; r++) acc[fm][f][r] = 0.f;

#pragma unroll 1
    for (int kc = 0; kc < 3; kc++) {
        __syncthreads();   // prior taps done reading A
        // ---- load A slab: 390 pixel-positions x 64 channels, predicated (SAME pad) ----
        const float* cnb = cn + (size_t)(b * CC + kc * 64) * HW;
#pragma unroll 1
        for (int pp = tid; pp < 390; pp += 256) {
            int yr = pp / 130, xx = pp - yr * 130;
            int gy = tile + yr - 1, gx = xx - 1;
            bool valid = ((unsigned)gy < HH) && ((unsigned)gx < WW);
            const float* src = cnb + (size_t)gy * WW + gx;
            char* aH = smem + CN_AH + (size_t)pp * AP;
            char* aL = smem + CN_AL + (size_t)pp * AP;
#pragma unroll
            for (int k0 = 0; k0 < 64; k0 += 2) {
                float v0 = valid ? src[(size_t)k0 * HW] : 0.f;
                float v1 = valid ? src[(size_t)(k0 + 1) * HW] : 0.f;
                uint32_t hi, lo;
                split_pair(v0, v1, hi, lo);
                *(uint32_t*)(aH + k0 * 2) = hi;
                *(uint32_t*)(aL + k0 * 2) = lo;
            }
        }
#pragma unroll 1
        for (int t9 = 0; t9 < 9; t9++) {
            __syncthreads();   // A visible (first tap) / prior tap mma done with B
            load_b_tile(g_w3t_h, g_w3t_l, (size_t)t9 * CC, kc * 64, smem, CN_BH, CN_BL, tid);
            __syncthreads();
            int dyi = t9 / 3, dxi = t9 % 3;
            uint32_t view = (uint32_t)((dyi * 130 + dxi) * AP);
            mma_chunk(sb, CN_AH + view, CN_AL + view, AP, CN_BH, CN_BL,
                      lane, mbase, nbase, acc);
        }
    }
    __syncthreads();
    epilogue_store(acc, smem, 0, g_cnf, (size_t)b * CC, tile * 128, tid, wid, lane);
}

// ================= qkv 1x1 GEMM (A persistent over 3 oc-groups) =================
#define Q_AH 0u
#define Q_PL (128 * APK)              // 51200 per plane
#define Q_AL Q_PL
#define Q_BH (2 * Q_PL)               // 102400
#define Q_BL (Q_BH + 192 * AP)        // 130048
#define Q_SMEM (Q_BL + 192 * AP)      // 157696

__global__ void __launch_bounds__(256, 1) k_gemm_qkv(const float* __restrict__ x) {
    extern __shared__ __align__(16) char smem[];
    uint32_t sb = smem_to_u32(smem);
    int tid = threadIdx.x, wid = tid >> 5, lane = tid & 31;
    int b = blockIdx.z, tile = blockIdx.x;
    int p0 = tile * 128;
    int mbase = (wid & 3) * 32, nbase = (wid >> 2) * 96;

    // ---- load full-K A panel once: [128 px][192 k] hi/lo ----
    {
        int m = tid & 127, g = tid >> 7;
        const float* a0 = x + (size_t)(b * CC) * HW + p0 + m;
        char* aH = smem + Q_AH + (size_t)m * APK;
        char* aL = smem + Q_AL + (size_t)m * APK;
#pragma unroll
        for (int i = 0; i < 48; i++) {
            int k0 = g * 96 + i * 2;
            float v0 = a0[(size_t)k0 * HW];
            float v1 = a0[(size_t)(k0 + 1) * HW];
            uint32_t hi, lo;
            split_pair(v0, v1, hi, lo);
            *(uint32_t*)(aH + k0 * 2) = hi;
            *(uint32_t*)(aL + k0 * 2) = lo;
        }
    }

#pragma unroll 1
    for (int grp = 0; grp < 3; grp++) {
        float acc[2][12][4];
#pragma unroll
        for (int fm = 0; fm < 2; fm++)
#pragma unroll
            for (int f = 0; f < 12; f++)
#pragma unroll
                for (int r = 0; r < 4; r++) acc[fm][f][r] = 0.f;

#pragma unroll 1
        for (int kc = 0; kc < 3; kc++) {
            __syncthreads();   // A visible / prior B consumers done / epilogue staging done
            load_b_tile(g_wq_h, g_wq_l, (size_t)grp * CC, kc * 64, smem, Q_BH, Q_BL, tid);
            __syncthreads();
            mma_chunk(sb, Q_AH + (uint32_t)(kc * 128), Q_AL + (uint32_t)(kc * 128), APK,
                      Q_BH, Q_BL, lane, mbase, nbase, acc);
        }
        __syncthreads();
        // staging aliases the B region (free until next grp's B load, which is sync-guarded)
        epilogue_store(acc, smem, Q_BH, g_mid, (size_t)b * C3 + grp * CC, p0, tid, wid, lane);
    }
}

// ================= final 1x1 GEMM (Wcomb @ v) =================
#define F_AH 0u
#define F_AL (128 * AP)               // 18432
#define F_BH (2 * 128 * AP)           // 36864
#define F_BL (F_BH + 192 * AP)        // 64512
#define F_SMEM (F_BL + 192 * AP)      // 92160

__global__ void __launch_bounds__(256, 1) k_gemm_fin(float* __restrict__ OutExt) {
    extern __shared__ __align__(16) char smem[];
    uint32_t sb = smem_to_u32(smem);
    int tid = threadIdx.x, wid = tid >> 5, lane = tid & 31;
    int b = blockIdx.z, tile = blockIdx.x;
    int p0 = tile * 128;
    int mbase = (wid & 3) * 32, nbase = (wid >> 2) * 96;

    float acc[2][12][4];
#pragma unroll
    for (int fm = 0; fm < 2; fm++)
#pragma unroll
        for (int f = 0; f < 12; f++)
#pragma unroll
            for (int r = 0; r < 4; r++) acc[fm][f][r] = 0.f;

#pragma unroll 1
    for (int kc = 0; kc < 3; kc++) {
        // ---- A tile: v channels [128 px][64 k] ----
        {
            int m = tid & 127, g = tid >> 7;
            const float* a0 = g_qkv + (size_t)(b * C3 + 2 * CC + kc * 64) * HW + p0 + m;
            char* aH = smem + F_AH + (size_t)m * AP;
            char* aL = smem + F_AL + (size_t)m * AP;
#pragma unroll
            for (int i = 0; i < 16; i++) {
                int k0 = g * 32 + i * 2;
                float v0 = a0[(size_t)k0 * HW];
                float v1 = a0[(size_t)(k0 + 1) * HW];
                uint32_t hi, lo;
                split_pair(v0, v1, hi, lo);
                *(uint32_t*)(aH + k0 * 2) = hi;
                *(uint32_t*)(aL + k0 * 2) = lo;
            }
        }
        load_b_tile(g_wcb_h, g_wcb_l, (size_t)b * CC, kc * 64, smem, F_BH, F_BL, tid);
        __syncthreads();
        mma_chunk(sb, F_AH, F_AL, AP, F_BH, F_BL, lane, mbase, nbase, acc);
        __syncthreads();
    }
    epilogue_store(acc, smem, 0, OutExt, (size_t)b * CC, p0, tid, wid, lane);
}

// ---------------- depthwise 3x3 (+ sumsq q/k/cn, dot(q,cn_f)) ----------------
__global__ void __launch_bounds__(256) k_dw(const float* __restrict__ dww) {
    __shared__ float sT[10][130];
    int y0 = blockIdx.x * 8;
    int oc = blockIdx.y;
    int b  = blockIdx.z;
    int tid = threadIdx.x;

    const float* mid = g_mid + (size_t)(b * C3 + oc) * HW;
    for (int idx = tid; idx < 10 * 130; idx += 256) {
        int r = idx / 130, cc = idx % 130;
        int y = y0 + r - 1, x = cc - 1;
        sT[r][cc] = ((unsigned)y < HH && (unsigned)x < WW) ? mid[y * WW + x] : 0.f;
    }
    float dw[9];
#pragma unroll
    for (int t = 0; t < 9; t++) dw[t] = dww[oc * 9 + t];
    __syncthreads();

    int py = tid >> 5, lane = tid & 31, xb = lane * 4;
    float out4[4];
#pragma unroll
    for (int j = 0; j < 4; j++) {
        float v = 0.f;
#pragma unroll
        for (int ky = 0; ky < 3; ky++)
#pragma unroll
            for (int kx = 0; kx < 3; kx++)
                v = fmaf(dw[ky * 3 + kx], sT[py + ky][xb + j + kx], v);
        out4[j] = v;
    }
    size_t base = (size_t)(b * C3 + oc) * HW + (y0 + py) * WW + xb;
#pragma unroll
    for (int j = 0; j < 4; j++) g_qkv[base + j] = out4[j];

    if (oc < 2 * CC) {
        float ss = 0.f, dd = 0.f, sc = 0.f;
#pragma unroll
        for (int j = 0; j < 4; j++) ss = fmaf(out4[j], out4[j], ss);
        if (oc < CC) {
            const float* cf = g_cnf + (size_t)(b * CC + oc) * HW + (y0 + py) * WW + xb;
#pragma unroll
            for (int j = 0; j < 4; j++) {
                float cv = cf[j];
                dd = fmaf(out4[j], cv, dd);
                sc = fmaf(cv, cv, sc);
            }
        }
        for (int off = 16; off; off >>= 1) {
            ss += __shfl_xor_sync(0xffffffffu, ss, off);
            dd += __shfl_xor_sync(0xffffffffu, dd, off);
            sc += __shfl_xor_sync(0xffffffffu, sc, off);
        }
        if (lane == 0) {
            if (oc < CC) {
                atomicAdd(&g_ssq[b * CC + oc], ss);
                atomicAdd(&g_dot[b * CC + oc], dd);
                atomicAdd(&g_sscn[b * CC + oc], sc);
            } else {
                atomicAdd(&g_ssk[b * CC + oc - CC], ss);
            }
        }
    }
}

// ---------------- attention GEMMs: S1 = q k^T, S2 = cn k^T ----------------
__global__ void __launch_bounds__(256) k_attn_gemm() {
    __shared__ float sQ[48][33], sK[48][33], sC[48][33];
    int b = blockIdx.z, h = blockIdx.y;
    int s0 = blockIdx.x * 1024;
    int tid = threadIdx.x;
    int ti = tid >> 4, tj = tid & 15;

    float a1[3][3] = {}, a2[3][3] = {};
    const float* qb = g_qkv + (size_t)(b * C3 + h * CH) * HW;
    const float* kb = g_qkv + (size_t)(b * C3 + CC + h * CH) * HW;
    const float* cb = g_cnf + (size_t)(b * CC + h * CH) * HW;

    for (int st = 0; st < 1024; st += 32) {
#pragma unroll
        for (int i = 0; i < 6; i++) {
            int idx = tid + i * 256;
            int r = idx >> 5, ss = idx & 31;
            sQ[r][ss] = qb[(size_t)r * HW + s0 + st + ss];
            sK[r][ss] = kb[(size_t)r * HW + s0 + st + ss];
            sC[r][ss] = cb[(size_t)r * HW + s0 + st + ss];
        }
        __syncthreads();
#pragma unroll 4
        for (int ss = 0; ss < 32; ss++) {
            float qv[3], kv[3], cv[3];
#pragma unroll
            for (int i = 0; i < 3; i++) {
                qv[i] = sQ[ti * 3 + i][ss];
                cv[i] = sC[ti * 3 + i][ss];
                kv[i] = sK[tj * 3 + i][ss];
            }
#pragma unroll
            for (int i = 0; i < 3; i++)
#pragma unroll
                for (int j = 0; j < 3; j++) {
                    a1[i][j] = fmaf(qv[i], kv[j], a1[i][j]);
                    a2[i][j] = fmaf(cv[i], kv[j], a2[i][j]);
                }
        }
        __syncthreads();
    }
    int base = ((b * NH + h) * CH) * CH;
#pragma unroll
    for (int i = 0; i < 3; i++)
#pragma unroll
        for (int j = 0; j < 3; j++) {
            atomicAdd(&g_S1[base + (ti * 3 + i) * CH + tj * 3 + j], a1[i][j]);
            atomicAdd(&g_S2[base + (ti * 3 + i) * CH + tj * 3 + j], a2[i][j]);
        }
}

// ---------------- finalize: normalize, softmax, Wcomb(hi/lo bf16) ----------------
__global__ void __launch_bounds__(256) k_finalize(const float* __restrict__ proj_w,
                                                  const float* __restrict__ temp) {
    __shared__ float L[CH * CH];
    __shared__ float rfA[CH], rfB[CH], cfc[CH];
    __shared__ float sWp[CC * CH];

    int h = blockIdx.x, b = blockIdx.y;
    int tid = threadIdx.x;

    if (tid < CH) {
        int gi = b * CC + h * CH + tid;
        float ssq = g_ssq[gi], sscn = g_sscn[gi], dt = g_dot[gi], ssk = g_ssk[gi];
        float a  = 1.f / fmaxf(sqrtf(ssq), EPSN);
        float bf = 1.f / fmaxf(sqrtf(sscn), EPSN);
        float ssum = ssq * a * a + sscn * bf * bf + 2.f * dt * a * bf;
        float inv_ns = 1.f / fmaxf(sqrtf(fmaxf(ssum, 0.f)), EPSN);
        rfA[tid] = a * inv_ns;
        rfB[tid] = bf * inv_ns;
        cfc[tid] = 1.f / fmaxf(sqrtf(ssk), EPSN);
    }
    __syncthreads();

    float tv = temp[h];
    int base = ((b * NH + h) * CH) * CH;
    for (int e = tid; e < CH * CH; e += 256) {
        int c = e / CH, d = e % CH;
        L[e] = (g_S1[base + e] * rfA[c] + g_S2[base + e] * rfB[c]) * cfc[d] * tv;
    }
    __syncthreads();

    int w = tid >> 5, lane = tid & 31;
    for (int k = 0; k < 6; k++) {
        int r = w * 6 + k;
        float v0 = L[r * CH + lane];
        float v1 = (lane < 16) ? L[r * CH + 32 + lane] : -1e30f;
        float m = fmaxf(v0, v1);
        for (int off = 16; off; off >>= 1) m = fmaxf(m, __shfl_xor_sync(0xffffffffu, m, off));
        float e0 = expf(v0 - m);
        float e1 = (lane < 16) ? expf(v1 - m) : 0.f;
        float s = e0 + e1;
        for (int off = 16; off; off >>= 1) s += __shfl_xor_sync(0xffffffffu, s, off);
        float inv = 1.f / s;
        L[r * CH + lane] = e0 * inv;
        if (lane < 16) L[r * CH + 32 + lane] = e1 * inv;
    }
    __syncthreads();

    for (int idx = tid; idx < CC * CH; idx += 256)
        sWp[idx] = proj_w[(idx / CH) * CC + h * CH + (idx % CH)];
    __syncthreads();
    for (int e = tid; e < CC * CH; e += 256) {
        int oc = e / CH, d = e % CH;
        float s = 0.f;
#pragma unroll 8
        for (int c = 0; c < CH; c++)
            s = fmaf(sWp[oc * CH + c], L[c * CH + d], s);
        size_t oe = ((size_t)b * CC + oc) * CC + h * CH + d;
        __nv_bfloat16 hv = __float2bfloat16(s);
        g_wcb_h[oe] = hv;
        g_wcb_l[oe] = __float2bfloat16(s - __bfloat162float(hv));
    }
}

// ---------------- launch ----------------
extern "C" void kernel_launch(void* const* d_in, const int* in_sizes, int n_in,
                              void* d_out, int out_size) {
    const float* x    = (const float*)d_in[0];
    const float* cn   = (const float*)d_in[1];
    const float* w1   = (const float*)d_in[2];
    const float* w3   = (const float*)d_in[3];
    const float* qw   = (const float*)d_in[4];
    const float* dww  = (const float*)d_in[5];
    const float* pw   = (const float*)d_in[6];
    const float* temp = (const float*)d_in[7];
    float* out = (float*)d_out;

    cudaFuncSetAttribute(k_gemm_cn,  cudaFuncAttributeMaxDynamicSharedMemorySize, CN_SMEM);
    cudaFuncSetAttribute(k_gemm_qkv, cudaFuncAttributeMaxDynamicSharedMemorySize, Q_SMEM);
    cudaFuncSetAttribute(k_gemm_fin, cudaFuncAttributeMaxDynamicSharedMemorySize, F_SMEM);

    k_init<<<288, 256>>>();
    k_compose<<<CC * 9, CC>>>(w1, w3);
    k_wprep<<<(C3 * CC + 255) / 256, 256>>>(qw);
    k_gemm_cn<<<dim3(128, 1, BB), 256, CN_SMEM>>>(cn);
    k_gemm_qkv<<<dim3(128, 1, BB), 256, Q_SMEM>>>(x);
    k_dw<<<dim3(HH / 8, C3, BB), 256>>>(dww);
    k_attn_gemm<<<dim3(HW / 1024, NH, BB), 256>>>();
    k_finalize<<<dim3(NH, BB), 256>>>(pw, temp);
    k_gemm_fin<<<dim3(128, 1, BB), 256, F_SMEM>>>(out);
}

// round 13
// speedup vs baseline: 3.0445x; 1.0162x over previous
#include <cuda_runtime.h>
#include <cuda_bf16.h>
#include <cstdint>
#include <math.h>

#define BB 8
#define CC 192
#define HH 128
#define WW 128
#define HW 16384
#define NH 4
#define CH 48
#define C3 576
#define EPSN 1e-12f

// ---------------- scratch (device globals; no allocs) ----------------
__device__ __align__(16) float g_cnf[(size_t)BB * CC * HW];
__device__ __align__(16) float g_mid[(size_t)BB * C3 * HW];
__device__ __align__(16) float g_qkv[(size_t)BB * C3 * HW];
__device__ float g_ssq[BB * CC];
__device__ float g_ssk[BB * CC];
__device__ float g_sscn[BB * CC];
__device__ float g_dot[BB * CC];
__device__ float g_S1[BB * NH * CH * CH];
__device__ float g_S2[BB * NH * CH * CH];
__device__ __align__(16) __nv_bfloat16 g_w3t_h[9 * CC * CC];   // [tap][oc][ic]
__device__ __align__(16) __nv_bfloat16 g_w3t_l[9 * CC * CC];
__device__ __align__(16) __nv_bfloat16 g_wq_h[C3 * CC];        // [oc][ic]
__device__ __align__(16) __nv_bfloat16 g_wq_l[C3 * CC];
__device__ __align__(16) __nv_bfloat16 g_wcb_h[BB * CC * CC];  // [b][oc][cin]
__device__ __align__(16) __nv_bfloat16 g_wcb_l[BB * CC * CC];

// ---------------- helpers ----------------
__device__ __forceinline__ uint32_t smem_to_u32(const void* p) {
    uint32_t a;
    asm("{ .reg .u64 t; cvta.to.shared.u64 t, %1; cvt.u32.u64 %0, t; }" : "=r"(a) : "l"(p));
    return a;
}
__device__ __forceinline__ void ldsm4(uint32_t* r, uint32_t addr) {
    asm volatile("ldmatrix.sync.aligned.m8n8.x4.shared.b16 {%0,%1,%2,%3}, [%4];"
                 : "=r"(r[0]), "=r"(r[1]), "=r"(r[2]), "=r"(r[3]) : "r"(addr));
}
__device__ __forceinline__ void mma16816(float* d, const uint32_t* a, uint32_t b0, uint32_t b1) {
    asm volatile(
        "mma.sync.aligned.m16n8k16.row.col.f32.bf16.bf16.f32 "
        "{%0,%1,%2,%3}, {%4,%5,%6,%7}, {%8,%9}, {%0,%1,%2,%3};"
        : "+f"(d[0]), "+f"(d[1]), "+f"(d[2]), "+f"(d[3])
        : "r"(a[0]), "r"(a[1]), "r"(a[2]), "r"(a[3]), "r"(b0), "r"(b1));
}
__device__ __forceinline__ uint32_t pack_bf2(__nv_bfloat16 a, __nv_bfloat16 b) {
    __nv_bfloat162 v = __halves2bfloat162(a, b);
    return *(uint32_t*)&v;
}
__device__ __forceinline__ void split_pair(float v0, float v1, uint32_t& hi, uint32_t& lo) {
    __nv_bfloat16 h0 = __float2bfloat16(v0), h1 = __float2bfloat16(v1);
    __nv_bfloat16 l0 = __float2bfloat16(v0 - __bfloat162float(h0));
    __nv_bfloat16 l1 = __float2bfloat16(v1 - __bfloat162float(h1));
    hi = pack_bf2(h0, h1);
    lo = pack_bf2(l0, l1);
}
__device__ __forceinline__ void cp_async16(uint32_t s, const void* g) {
    asm volatile("cp.async.cg.shared.global [%0], [%1], 16;" :: "r"(s), "l"(g) : "memory");
}
#define CP_COMMIT() asm volatile("cp.async.commit_group;" ::: "memory")
#define CP_WAIT1()  asm volatile("cp.async.wait_group 1;" ::: "memory")
#define CP_WAIT0()  asm volatile("cp.async.wait_group 0;" ::: "memory")

#define AP 144      // B/A row pitch for 64-k tiles (128B data + 16 pad)
#define APK 400     // A row pitch for full K=192 (384B data + 16 pad)

// async B tile loader: [192 rows][64 k] hi+lo -> smem pitch AP via cp.async
__device__ __forceinline__ void load_b_async(const __nv_bfloat16* __restrict__ bhp,
                                             const __nv_bfloat16* __restrict__ blp,
                                             size_t row0, int koff,
                                             uint32_t sBH, uint32_t sBL, int tid) {
#pragma unroll
    for (int i = 0; i < 6; i++) {
        int idx = tid + i * 256;
        int r = idx >> 3, gg = idx & 7;
        size_t e = (row0 + r) * CC + koff + gg * 8;
        cp_async16(sBH + r * AP + gg * 16, bhp + e);
        cp_async16(sBL + r * AP + gg * 16, blp + e);
    }
}

// MMA over one 64-k chunk. aBaseH/aBaseL include view & column base offsets; row stride = astride.
__device__ __forceinline__ void mma_chunk(uint32_t sb, uint32_t aBaseH, uint32_t aBaseL,
                                          uint32_t astride, uint32_t offBH, uint32_t offBL,
                                          int lane, int mbase, int nbase, float acc[2][12][4]) {
#pragma unroll
    for (int kk = 0; kk < 64; kk += 16) {
        uint32_t afh[2][4], afl[2][4];
#pragma unroll
        for (int fm = 0; fm < 2; fm++) {
            uint32_t rel = (uint32_t)((mbase + fm * 16 + (lane & 15)) * astride
                         + (kk + ((lane >> 4) << 3)) * 2);
            ldsm4(afh[fm], sb + aBaseH + rel);
            ldsm4(afl[fm], sb + aBaseL + rel);
        }
#pragma unroll
        for (int fn2 = 0; fn2 < 6; fn2++) {
            uint32_t bh4[4], bl4[4];
            uint32_t rowb = (uint32_t)((nbase + fn2 * 16 + (lane & 7) + ((lane >> 4) << 3)) * AP
                           + (kk + (((lane >> 3) & 1) << 3)) * 2);
            ldsm4(bh4, sb + offBH + rowb);
            ldsm4(bl4, sb + offBL + rowb);
#pragma unroll
            for (int fm = 0; fm < 2; fm++) {
#pragma unroll
                for (int s2 = 0; s2 < 2; s2++) {
                    float* d = acc[fm][fn2 * 2 + s2];
                    mma16816(d, afh[fm], bh4[s2 * 2], bh4[s2 * 2 + 1]);
                    mma16816(d, afh[fm], bl4[s2 * 2], bl4[s2 * 2 + 1]);
                    mma16816(d, afl[fm], bh4[s2 * 2], bh4[s2 * 2 + 1]);
                }
            }
        }
    }
}

// epilogue: transpose-stage through smem, coalesced channel-major stores
__device__ __forceinline__ void epilogue_store(float acc[2][12][4], char* smem, uint32_t stgOff,
                                               float* __restrict__ Outp, size_t ocb, int p0,
                                               int tid, int wid, int lane) {
    float* stg = (float*)(smem + stgOff);
    int mw = wid & 3, nw = wid >> 2;
    int mbase = mw * 32;
#pragma unroll
    for (int h = 0; h < 2; h++) {
        if (nw == h) {
#pragma unroll
            for (int fm = 0; fm < 2; fm++)
#pragma unroll
                for (int f = 0; f < 12; f++) {
                    int nl = f * 8 + 2 * (lane & 3);
                    int mr = mbase + fm * 16 + (lane >> 2);
                    float* a = acc[fm][f];
                    stg[nl * 132 + mr]           = a[0];
                    stg[(nl + 1) * 132 + mr]     = a[1];
                    stg[nl * 132 + mr + 8]       = a[2];
                    stg[(nl + 1) * 132 + mr + 8] = a[3];
                }
        }
        __syncthreads();
#pragma unroll
        for (int r = 0; r < 48; r++) {
            int flat = tid + r * 256;
            int mm = flat & 127, nn = flat >> 7;
            Outp[(ocb + h * 96 + nn) * (size_t)HW + p0 + mm] = stg[nn * 132 + mm];
        }
        __syncthreads();
    }
}

// ---------------- init ----------------
__global__ void k_init() {
    int i = blockIdx.x * blockDim.x + threadIdx.x;
    if (i < BB * CC) { g_ssq[i] = 0.f; g_ssk[i] = 0.f; g_sscn[i] = 0.f; g_dot[i] = 0.f; }
    int n2 = BB * NH * CH * CH;
    for (int j = i; j < n2; j += gridDim.x * blockDim.x) { g_S1[j] = 0.f; g_S2[j] = 0.f; }
}

// ---------------- compose cn weights -> bf16 hi/lo [tap][oc][ic] ----------------
__global__ void k_compose(const float* __restrict__ w1, const float* __restrict__ w3) {
    int o = blockIdx.x / 9;
    int t = blockIdx.x % 9;
    int i = threadIdx.x;
    float acc = 0.f;
    for (int m = 0; m < CC; m++)
        acc = fmaf(w3[(o * CC + m) * 9 + t], w1[m * CC + i], acc);
    __nv_bfloat16 h = __float2bfloat16(acc);
    __nv_bfloat16 l = __float2bfloat16(acc - __bfloat162float(h));
    size_t e = ((size_t)t * CC + o) * CC + i;
    g_w3t_h[e] = h; g_w3t_l[e] = l;
}

// ---------------- qkv weight prep ----------------
__global__ void k_wprep(const float* __restrict__ qw) {
    int i = blockIdx.x * blockDim.x + threadIdx.x;
    if (i >= C3 * CC) return;
    float v = qw[i];
    __nv_bfloat16 h = __float2bfloat16(v);
    g_wq_h[i] = h;
    g_wq_l[i] = __float2bfloat16(v - __bfloat162float(h));
}

// ================= cn conv 3x3 GEMM (double-buffered async B) =================
#define CN_AH 0u
#define CN_PL (3 * 130 * AP)              // 56160 per A plane
#define CN_AL CN_PL
#define CN_B0H (2 * CN_PL)                // 112320
#define CN_B0L (CN_B0H + 192 * AP)        // 139968
#define CN_B1H (CN_B0L + 192 * AP)        // 167616
#define CN_B1L (CN_B1H + 192 * AP)        // 195264
#define CN_SMEM (CN_B1L + 192 * AP)       // 222912

__global__ void __launch_bounds__(256, 1) k_gemm_cn(const float* __restrict__ cn) {
    extern __shared__ __align__(16) char smem[];
    uint32_t sb = smem_to_u32(smem);
    int tid = threadIdx.x, wid = tid >> 5, lane = tid & 31;
    int b = blockIdx.z, tile = blockIdx.x;
    int mbase = (wid & 3) * 32, nbase = (wid >> 2) * 96;

    float acc[2][12][4];
#pragma unroll
    for (int fm = 0; fm < 2; fm++)
#pragma unroll
        for (int f = 0; f < 12; f++)
#pragma unroll
            for (int r = 0; r < 4; r++) acc[fm][f][r] = 0.f;

    // prefetch B for chunk 0 (tap 0, kc 0) into buf0
    load_b_async(g_w3t_h, g_w3t_l, 0, 0, sb + CN_B0H, sb + CN_B0L, tid);
    CP_COMMIT();

#pragma unroll 1
    for (int kc = 0; kc < 3; kc++) {
        // ---- load A slab: 390 pixel-positions x 64 channels, predicated (SAME pad) ----
        // (prior chunk's trailing sync guarantees A consumers are done)
        const float* cnb = cn + (size_t)(b * CC + kc * 64) * HW;
#pragma unroll 1
        for (int pp = tid; pp < 390; pp += 256) {
            int yr = pp / 130, xx = pp - yr * 130;
            int gy = tile + yr - 1, gx = xx - 1;
            bool valid = ((unsigned)gy < HH) && ((unsigned)gx < WW);
            const float* src = cnb + (size_t)gy * WW + gx;
            char* aH = smem + CN_AH + (size_t)pp * AP;
            char* aL = smem + CN_AL + (size_t)pp * AP;
#pragma unroll
            for (int k0 = 0; k0 < 64; k0 += 2) {
                float v0 = valid ? src[(size_t)k0 * HW] : 0.f;
                float v1 = valid ? src[(size_t)(k0 + 1) * HW] : 0.f;
                uint32_t hi, lo;
                split_pair(v0, v1, hi, lo);
                *(uint32_t*)(aH + k0 * 2) = hi;
                *(uint32_t*)(aL + k0 * 2) = lo;
            }
        }
#pragma unroll 1
        for (int t9 = 0; t9 < 9; t9++) {
            int c = kc * 9 + t9;
            if (c < 26) {
                int c2 = c + 1;
                int k2 = c2 / 9, t2 = c2 - k2 * 9;
                load_b_async(g_w3t_h, g_w3t_l, (size_t)t2 * CC, k2 * 64,
                             sb + ((c2 & 1) ? CN_B1H : CN_B0H),
                             sb + ((c2 & 1) ? CN_B1L : CN_B0L), tid);
                CP_COMMIT();
                CP_WAIT1();
            } else {
                CP_WAIT0();
            }
            __syncthreads();   // buf[c&1] + (first tap) A slab visible
            int dyi = t9 / 3, dxi = t9 % 3;
            uint32_t view = (uint32_t)((dyi * 130 + dxi) * AP);
            mma_chunk(sb, CN_AH + view, CN_AL + view, AP,
                      (c & 1) ? CN_B1H : CN_B0H, (c & 1) ? CN_B1L : CN_B0L,
                      lane, mbase, nbase, acc);
            __syncthreads();   // mma done before buf[c&1] overwritten / A reloaded
        }
    }
    epilogue_store(acc, smem, 0, g_cnf, (size_t)b * CC, tile * 128, tid, wid, lane);
}

// ================= qkv 1x1 GEMM (A persistent, async B over 9 chunks) =================
#define Q_AH 0u
#define Q_PL (128 * APK)                  // 51200 per A plane
#define Q_AL Q_PL
#define Q_B0H (2 * Q_PL)                  // 102400
#define Q_B0L (Q_B0H + 192 * AP)          // 130048
#define Q_B1H (Q_B0L + 192 * AP)          // 157696
#define Q_B1L (Q_B1H + 192 * AP)          // 185344
#define Q_SMEM (Q_B1L + 192 * AP)         // 212992

__global__ void __launch_bounds__(256, 1) k_gemm_qkv(const float* __restrict__ x) {
    extern __shared__ __align__(16) char smem[];
    uint32_t sb = smem_to_u32(smem);
    int tid = threadIdx.x, wid = tid >> 5, lane = tid & 31;
    int b = blockIdx.z, tile = blockIdx.x;
    int p0 = tile * 128;
    int mbase = (wid & 3) * 32, nbase = (wid >> 2) * 96;

    // prefetch B chunk 0 (grp0, kc0)
    load_b_async(g_wq_h, g_wq_l, 0, 0, sb + Q_B0H, sb + Q_B0L, tid);
    CP_COMMIT();

    // ---- load full-K A panel once: [128 px][192 k] hi/lo (overlaps prefetch) ----
    {
        int m = tid & 127, g = tid >> 7;
        const float* a0 = x + (size_t)(b * CC) * HW + p0 + m;
        char* aH = smem + Q_AH + (size_t)m * APK;
        char* aL = smem + Q_AL + (size_t)m * APK;
#pragma unroll
        for (int i = 0; i < 48; i++) {
            int k0 = g * 96 + i * 2;
            float v0 = a0[(size_t)k0 * HW];
            float v1 = a0[(size_t)(k0 + 1) * HW];
            uint32_t hi, lo;
            split_pair(v0, v1, hi, lo);
            *(uint32_t*)(aH + k0 * 2) = hi;
            *(uint32_t*)(aL + k0 * 2) = lo;
        }
    }

#pragma unroll 1
    for (int grp = 0; grp < 3; grp++) {
        float acc[2][12][4];
#pragma unroll
        for (int fm = 0; fm < 2; fm++)
#pragma unroll
            for (int f = 0; f < 12; f++)
#pragma unroll
                for (int r = 0; r < 4; r++) acc[fm][f][r] = 0.f;

#pragma unroll 1
        for (int kc = 0; kc < 3; kc++) {
            int c = grp * 3 + kc;
            if (c < 8) {
                int c2 = c + 1;
                int g2 = c2 / 3, k2 = c2 - g2 * 3;
                load_b_async(g_wq_h, g_wq_l, (size_t)g2 * CC, k2 * 64,
                             sb + ((c2 & 1) ? Q_B1H : Q_B0H),
                             sb + ((c2 & 1) ? Q_B1L : Q_B0L), tid);
                CP_COMMIT();
                CP_WAIT1();
            } else {
                CP_WAIT0();
            }
            __syncthreads();
            mma_chunk(sb, Q_AH + (uint32_t)(kc * 128), Q_AL + (uint32_t)(kc * 128), APK,
                      (c & 1) ? Q_B1H : Q_B0H, (c & 1) ? Q_B1L : Q_B0L,
                      lane, mbase, nbase, acc);
            __syncthreads();
        }
        // stage epilogue in the just-consumed B buffer (prefetch lives in the other)
        uint32_t stgOff = (((grp * 3 + 2) & 1) ? Q_B1H : Q_B0H);
        epilogue_store(acc, smem, stgOff, g_mid, (size_t)b * C3 + grp * CC, p0, tid, wid, lane);
    }
}

// ================= final 1x1 GEMM (Wcomb @ v, async B) =================
#define F_AH 0u
#define F_AL (128 * AP)                   // 18432
#define F_B0H (2 * 128 * AP)              // 36864
#define F_B0L (F_B0H + 192 * AP)          // 64512
#define F_B1H (F_B0L + 192 * AP)          // 92160
#define F_B1L (F_B1H + 192 * AP)          // 119808
#define F_SMEM (F_B1L + 192 * AP)         // 147456

__global__ void __launch_bounds__(256, 1) k_gemm_fin(float* __restrict__ OutExt) {
    extern __shared__ __align__(16) char smem[];
    uint32_t sb = smem_to_u32(smem);
    int tid = threadIdx.x, wid = tid >> 5, lane = tid & 31;
    int b = blockIdx.z, tile = blockIdx.x;
    int p0 = tile * 128;
    int mbase = (wid & 3) * 32, nbase = (wid >> 2) * 96;

    float acc[2][12][4];
#pragma unroll
    for (int fm = 0; fm < 2; fm++)
#pragma unroll
        for (int f = 0; f < 12; f++)
#pragma unroll
            for (int r = 0; r < 4; r++) acc[fm][f][r] = 0.f;

    load_b_async(g_wcb_h, g_wcb_l, (size_t)b * CC, 0, sb + F_B0H, sb + F_B0L, tid);
    CP_COMMIT();

#pragma unroll 1
    for (int kc = 0; kc < 3; kc++) {
        if (kc < 2) {
            load_b_async(g_wcb_h, g_wcb_l, (size_t)b * CC, (kc + 1) * 64,
                         sb + (((kc + 1) & 1) ? F_B1H : F_B0H),
                         sb + (((kc + 1) & 1) ? F_B1L : F_B0L), tid);
            CP_COMMIT();
        }
        // ---- A tile: v channels [128 px][64 k] (overlaps cp.async) ----
        {
            int m = tid & 127, g = tid >> 7;
            const float* a0 = g_qkv + (size_t)(b * C3 + 2 * CC + kc * 64) * HW + p0 + m;
            char* aH = smem + F_AH + (size_t)m * AP;
            char* aL = smem + F_AL + (size_t)m * AP;
#pragma unroll
            for (int i = 0; i < 16; i++) {
                int k0 = g * 32 + i * 2;
                float v0 = a0[(size_t)k0 * HW];
                float v1 = a0[(size_t)(k0 + 1) * HW];
                uint32_t hi, lo;
                split_pair(v0, v1, hi, lo);
                *(uint32_t*)(aH + k0 * 2) = hi;
                *(uint32_t*)(aL + k0 * 2) = lo;
            }
        }
        if (kc < 2) { CP_WAIT1(); } else { CP_WAIT0(); }
        __syncthreads();
        mma_chunk(sb, F_AH, F_AL, AP,
                  (kc & 1) ? F_B1H : F_B0H, (kc & 1) ? F_B1L : F_B0L,
                  lane, mbase, nbase, acc);
        __syncthreads();   // mma done before A overwritten next kc
    }
    epilogue_store(acc, smem, 0, OutExt, (size_t)b * CC, p0, tid, wid, lane);
}

// ---------------- depthwise 3x3 (+ sumsq q/k/cn, dot(q,cn_f)) ----------------
__global__ void __launch_bounds__(256) k_dw(const float* __restrict__ dww) {
    __shared__ float sT[10][130];
    int y0 = blockIdx.x * 8;
    int oc = blockIdx.y;
    int b  = blockIdx.z;
    int tid = threadIdx.x;

    const float* mid = g_mid + (size_t)(b * C3 + oc) * HW;
    for (int idx = tid; idx < 10 * 130; idx += 256) {
        int r = idx / 130, cc = idx % 130;
        int y = y0 + r - 1, x = cc - 1;
        sT[r][cc] = ((unsigned)y < HH && (unsigned)x < WW) ? mid[y * WW + x] : 0.f;
    }
    float dw[9];
#pragma unroll
    for (int t = 0; t < 9; t++) dw[t] = dww[oc * 9 + t];
    __syncthreads();

    int py = tid >> 5, lane = tid & 31, xb = lane * 4;
    float out4[4];
#pragma unroll
    for (int j = 0; j < 4; j++) {
        float v = 0.f;
#pragma unroll
        for (int ky = 0; ky < 3; ky++)
#pragma unroll
            for (int kx = 0; kx < 3; kx++)
                v = fmaf(dw[ky * 3 + kx], sT[py + ky][xb + j + kx], v);
        out4[j] = v;
    }
    size_t base = (size_t)(b * C3 + oc) * HW + (y0 + py) * WW + xb;
#pragma unroll
    for (int j = 0; j < 4; j++) g_qkv[base + j] = out4[j];

    if (oc < 2 * CC) {
        float ss = 0.f, dd = 0.f, sc = 0.f;
#pragma unroll
        for (int j = 0; j < 4; j++) ss = fmaf(out4[j], out4[j], ss);
        if (oc < CC) {
            const float* cf = g_cnf + (size_t)(b * CC + oc) * HW + (y0 + py) * WW + xb;
#pragma unroll
            for (int j = 0; j < 4; j++) {
                float cv = cf[j];
                dd = fmaf(out4[j], cv, dd);
                sc = fmaf(cv, cv, sc);
            }
        }
        for (int off = 16; off; off >>= 1) {
            ss += __shfl_xor_sync(0xffffffffu, ss, off);
            dd += __shfl_xor_sync(0xffffffffu, dd, off);
            sc += __shfl_xor_sync(0xffffffffu, sc, off);
        }
        if (lane == 0) {
            if (oc < CC) {
                atomicAdd(&g_ssq[b * CC + oc], ss);
                atomicAdd(&g_dot[b * CC + oc], dd);
                atomicAdd(&g_sscn[b * CC + oc], sc);
            } else {
                atomicAdd(&g_ssk[b * CC + oc - CC], ss);
            }
        }
    }
}

// ---------------- attention GEMMs: S1 = q k^T, S2 = cn k^T ----------------
__global__ void __launch_bounds__(256) k_attn_gemm() {
    __shared__ float sQ[48][33], sK[48][33], sC[48][33];
    int b = blockIdx.z, h = blockIdx.y;
    int s0 = blockIdx.x * 1024;
    int tid = threadIdx.x;
    int ti = tid >> 4, tj = tid & 15;

    float a1[3][3] = {}, a2[3][3] = {};
    const float* qb = g_qkv + (size_t)(b * C3 + h * CH) * HW;
    const float* kb = g_qkv + (size_t)(b * C3 + CC + h * CH) * HW;
    const float* cb = g_cnf + (size_t)(b * CC + h * CH) * HW;

    for (int st = 0; st < 1024; st += 32) {
#pragma unroll
        for (int i = 0; i < 6; i++) {
            int idx = tid + i * 256;
            int r = idx >> 5, ss = idx & 31;
            sQ[r][ss] = qb[(size_t)r * HW + s0 + st + ss];
            sK[r][ss] = kb[(size_t)r * HW + s0 + st + ss];
            sC[r][ss] = cb[(size_t)r * HW + s0 + st + ss];
        }
        __syncthreads();
#pragma unroll 4
        for (int ss = 0; ss < 32; ss++) {
            float qv[3], kv[3], cv[3];
#pragma unroll
            for (int i = 0; i < 3; i++) {
                qv[i] = sQ[ti * 3 + i][ss];
                cv[i] = sC[ti * 3 + i][ss];
                kv[i] = sK[tj * 3 + i][ss];
            }
#pragma unroll
            for (int i = 0; i < 3; i++)
#pragma unroll
                for (int j = 0; j < 3; j++) {
                    a1[i][j] = fmaf(qv[i], kv[j], a1[i][j]);
                    a2[i][j] = fmaf(cv[i], kv[j], a2[i][j]);
                }
        }
        __syncthreads();
    }
    int base = ((b * NH + h) * CH) * CH;
#pragma unroll
    for (int i = 0; i < 3; i++)
#pragma unroll
        for (int j = 0; j < 3; j++) {
            atomicAdd(&g_S1[base + (ti * 3 + i) * CH + tj * 3 + j], a1[i][j]);
            atomicAdd(&g_S2[base + (ti * 3 + i) * CH + tj * 3 + j], a2[i][j]);
        }
}

// ---------------- finalize: normalize, softmax, Wcomb(hi/lo bf16) ----------------
__global__ void __launch_bounds__(256) k_finalize(const float* __restrict__ proj_w,
                                                  const float* __restrict__ temp) {
    __shared__ float L[CH * CH];
    __shared__ float rfA[CH], rfB[CH], cfc[CH];
    __shared__ float sWp[CC * CH];

    int h = blockIdx.x, b = blockIdx.y;
    int tid = threadIdx.x;

    if (tid < CH) {
        int gi = b * CC + h * CH + tid;
        float ssq = g_ssq[gi], sscn = g_sscn[gi], dt = g_dot[gi], ssk = g_ssk[gi];
        float a  = 1.f / fmaxf(sqrtf(ssq), EPSN);
        float bf = 1.f / fmaxf(sqrtf(sscn), EPSN);
        float ssum = ssq * a * a + sscn * bf * bf + 2.f * dt * a * bf;
        float inv_ns = 1.f / fmaxf(sqrtf(fmaxf(ssum, 0.f)), EPSN);
        rfA[tid] = a * inv_ns;
        rfB[tid] = bf * inv_ns;
        cfc[tid] = 1.f / fmaxf(sqrtf(ssk), EPSN);
    }
    __syncthreads();

    float tv = temp[h];
    int base = ((b * NH + h) * CH) * CH;
    for (int e = tid; e < CH * CH; e += 256) {
        int c = e / CH, d = e % CH;
        L[e] = (g_S1[base + e] * rfA[c] + g_S2[base + e] * rfB[c]) * cfc[d] * tv;
    }
    __syncthreads();

    int w = tid >> 5, lane = tid & 31;
    for (int k = 0; k < 6; k++) {
        int r = w * 6 + k;
        float v0 = L[r * CH + lane];
        float v1 = (lane < 16) ? L[r * CH + 32 + lane] : -1e30f;
        float m = fmaxf(v0, v1);
        for (int off = 16; off; off >>= 1) m = fmaxf(m, __shfl_xor_sync(0xffffffffu, m, off));
        float e0 = expf(v0 - m);
        float e1 = (lane < 16) ? expf(v1 - m) : 0.f;
        float s = e0 + e1;
        for (int off = 16; off; off >>= 1) s += __shfl_xor_sync(0xffffffffu, s, off);
        float inv = 1.f / s;
        L[r * CH + lane] = e0 * inv;
        if (lane < 16) L[r * CH + 32 + lane] = e1 * inv;
    }
    __syncthreads();

    for (int idx = tid; idx < CC * CH; idx += 256)
        sWp[idx] = proj_w[(idx / CH) * CC + h * CH + (idx % CH)];
    __syncthreads();
    for (int e = tid; e < CC * CH; e += 256) {
        int oc = e / CH, d = e % CH;
        float s = 0.f;
#pragma unroll 8
        for (int c = 0; c < CH; c++)
            s = fmaf(sWp[oc * CH + c], L[c * CH + d], s);
        size_t oe = ((size_t)b * CC + oc) * CC + h * CH + d;
        __nv_bfloat16 hv = __float2bfloat16(s);
        g_wcb_h[oe] = hv;
        g_wcb_l[oe] = __float2bfloat16(s - __bfloat162float(hv));
    }
}

// ---------------- launch ----------------
extern "C" void kernel_launch(void* const* d_in, const int* in_sizes, int n_in,
                              void* d_out, int out_size) {
    const float* x    = (const float*)d_in[0];
    const float* cn   = (const float*)d_in[1];
    const float* w1   = (const float*)d_in[2];
    const float* w3   = (const float*)d_in[3];
    const float* qw   = (const float*)d_in[4];
    const float* dww  = (const float*)d_in[5];
    const float* pw   = (const float*)d_in[6];
    const float* temp = (const float*)d_in[7];
    float* out = (float*)d_out;

    cudaFuncSetAttribute(k_gemm_cn,  cudaFuncAttributeMaxDynamicSharedMemorySize, CN_SMEM);
    cudaFuncSetAttribute(k_gemm_qkv, cudaFuncAttributeMaxDynamicSharedMemorySize, Q_SMEM);
    cudaFuncSetAttribute(k_gemm_fin, cudaFuncAttributeMaxDynamicSharedMemorySize, F_SMEM);

    k_init<<<288, 256>>>();
    k_compose<<<CC * 9, CC>>>(w1, w3);
    k_wprep<<<(C3 * CC + 255) / 256, 256>>>(qw);
    k_gemm_cn<<<dim3(128, 1, BB), 256, CN_SMEM>>>(cn);
    k_gemm_qkv<<<dim3(128, 1, BB), 256, Q_SMEM>>>(x);
    k_dw<<<dim3(HH / 8, C3, BB), 256>>>(dww);
    k_attn_gemm<<<dim3(HW / 1024, NH, BB), 256>>>();
    k_finalize<<<dim3(NH, BB), 256>>>(pw, temp);
    k_gemm_fin<<<dim3(128, 1, BB), 256, F_SMEM>>>(out);
}

// round 17
// speedup vs baseline: 3.0913x; 1.0154x over previous
#include <cuda_runtime.h>
#include <cuda_bf16.h>
#include <cstdint>
#include <math.h>

#define BB 8
#define CC 192
#define HH 128
#define WW 128
#define HW 16384
#define NH 4
#define CH 48
#define C3 576
#define EPSN 1e-12f

// ---------------- scratch (device globals; no allocs) ----------------
__device__ __align__(16) float g_cnf[(size_t)BB * CC * HW];
__device__ __align__(16) float g_mid[(size_t)BB * C3 * HW];
__device__ __align__(16) float g_qkv[(size_t)BB * C3 * HW];
__device__ float g_ssq[BB * CC];
__device__ float g_ssk[BB * CC];
__device__ float g_sscn[BB * CC];
__device__ float g_dot[BB * CC];
__device__ float g_S1[BB * NH * CH * CH];
__device__ float g_S2[BB * NH * CH * CH];
__device__ __align__(16) __nv_bfloat16 g_w3t_h[9 * CC * CC];   // [tap][oc][ic]
__device__ __align__(16) __nv_bfloat16 g_w3t_l[9 * CC * CC];
__device__ __align__(16) __nv_bfloat16 g_wq_h[C3 * CC];        // [oc][ic]
__device__ __align__(16) __nv_bfloat16 g_wq_l[C3 * CC];
__device__ __align__(16) __nv_bfloat16 g_wcb_h[BB * CC * CC];  // [b][oc][cin]
__device__ __align__(16) __nv_bfloat16 g_wcb_l[BB * CC * CC];

// ---------------- helpers ----------------
__device__ __forceinline__ uint32_t smem_to_u32(const void* p) {
    uint32_t a;
    asm("{ .reg .u64 t; cvta.to.shared.u64 t, %1; cvt.u32.u64 %0, t; }" : "=r"(a) : "l"(p));
    return a;
}
__device__ __forceinline__ void ldsm4(uint32_t* r, uint32_t addr) {
    asm volatile("ldmatrix.sync.aligned.m8n8.x4.shared.b16 {%0,%1,%2,%3}, [%4];"
                 : "=r"(r[0]), "=r"(r[1]), "=r"(r[2]), "=r"(r[3]) : "r"(addr));
}
__device__ __forceinline__ void mma16816(float* d, const uint32_t* a, uint32_t b0, uint32_t b1) {
    asm volatile(
        "mma.sync.aligned.m16n8k16.row.col.f32.bf16.bf16.f32 "
        "{%0,%1,%2,%3}, {%4,%5,%6,%7}, {%8,%9}, {%0,%1,%2,%3};"
        : "+f"(d[0]), "+f"(d[1]), "+f"(d[2]), "+f"(d[3])
        : "r"(a[0]), "r"(a[1]), "r"(a[2]), "r"(a[3]), "r"(b0), "r"(b1));
}
__device__ __forceinline__ uint32_t pack_bf2(__nv_bfloat16 a, __nv_bfloat16 b) {
    __nv_bfloat162 v = __halves2bfloat162(a, b);
    return *(uint32_t*)&v;
}
__device__ __forceinline__ void split_pair(float v0, float v1, uint32_t& hi, uint32_t& lo) {
    __nv_bfloat16 h0 = __float2bfloat16(v0), h1 = __float2bfloat16(v1);
    __nv_bfloat16 l0 = __float2bfloat16(v0 - __bfloat162float(h0));
    __nv_bfloat16 l1 = __float2bfloat16(v1 - __bfloat162float(h1));
    hi = pack_bf2(h0, h1);
    lo = pack_bf2(l0, l1);
}
__device__ __forceinline__ void cp_async16(uint32_t s, const void* g) {
    asm volatile("cp.async.cg.shared.global [%0], [%1], 16;" :: "r"(s), "l"(g) : "memory");
}
#define CP_COMMIT() asm volatile("cp.async.commit_group;" ::: "memory")
#define CP_WAIT1()  asm volatile("cp.async.wait_group 1;" ::: "memory")
#define CP_WAIT0()  asm volatile("cp.async.wait_group 0;" ::: "memory")

#define AP 144      // B/A row pitch for 64-k tiles (128B data + 16 pad)
#define APK 400     // A row pitch for full K=192 (384B data + 16 pad)
#define NT 512      // threads per GEMM CTA (16 warps: 4m x 4n)

// async B tile loader: [192 rows][64 k] hi+lo -> smem pitch AP via cp.async (512 thr)
__device__ __forceinline__ void load_b_async(const __nv_bfloat16* __restrict__ bhp,
                                             const __nv_bfloat16* __restrict__ blp,
                                             size_t row0, int koff,
                                             uint32_t sBH, uint32_t sBL, int tid) {
#pragma unroll
    for (int i = 0; i < 3; i++) {
        int idx = tid + i * NT;
        int r = idx >> 3, gg = idx & 7;
        size_t e = (row0 + r) * CC + koff + gg * 8;
        cp_async16(sBH + r * AP + gg * 16, bhp + e);
        cp_async16(sBL + r * AP + gg * 16, blp + e);
    }
}

// MMA over one 64-k chunk; warp tile 32(m) x 48(n).
__device__ __forceinline__ void mma_chunk(uint32_t sb, uint32_t aBaseH, uint32_t aBaseL,
                                          uint32_t astride, uint32_t offBH, uint32_t offBL,
                                          int lane, int mbase, int nbase, float acc[2][6][4]) {
#pragma unroll
    for (int kk = 0; kk < 64; kk += 16) {
        uint32_t afh[2][4], afl[2][4];
#pragma unroll
        for (int fm = 0; fm < 2; fm++) {
            uint32_t rel = (uint32_t)((mbase + fm * 16 + (lane & 15)) * astride
                         + (kk + ((lane >> 4) << 3)) * 2);
            ldsm4(afh[fm], sb + aBaseH + rel);
            ldsm4(afl[fm], sb + aBaseL + rel);
        }
#pragma unroll
        for (int fn2 = 0; fn2 < 3; fn2++) {
            uint32_t bh4[4], bl4[4];
            uint32_t rowb = (uint32_t)((nbase + fn2 * 16 + (lane & 7) + ((lane >> 4) << 3)) * AP
                           + (kk + (((lane >> 3) & 1) << 3)) * 2);
            ldsm4(bh4, sb + offBH + rowb);
            ldsm4(bl4, sb + offBL + rowb);
#pragma unroll
            for (int fm = 0; fm < 2; fm++) {
#pragma unroll
                for (int s2 = 0; s2 < 2; s2++) {
                    float* d = acc[fm][fn2 * 2 + s2];
                    mma16816(d, afh[fm], bh4[s2 * 2], bh4[s2 * 2 + 1]);
                    mma16816(d, afh[fm], bl4[s2 * 2], bl4[s2 * 2 + 1]);
                    mma16816(d, afl[fm], bh4[s2 * 2], bh4[s2 * 2 + 1]);
                }
            }
        }
    }
}

// epilogue (16 warps): two 96-col phases; staging buffer 96*132*4 = 50688 B at stgOff.
__device__ __forceinline__ void epilogue_store(float acc[2][6][4], char* smem, uint32_t stgOff,
                                               float* __restrict__ Outp, size_t ocb, int p0,
                                               int tid, int wid, int lane) {
    float* stg = (float*)(smem + stgOff);
    int mw = wid & 3, nw = wid >> 2;
    int mbase = mw * 32;
#pragma unroll
    for (int h = 0; h < 2; h++) {
        if ((nw >> 1) == h) {
            int nloc = (nw & 1) * 48;
#pragma unroll
            for (int fm = 0; fm < 2; fm++)
#pragma unroll
                for (int f = 0; f < 6; f++) {
                    int nl = nloc + f * 8 + 2 * (lane & 3);
                    int mr = mbase + fm * 16 + (lane >> 2);
                    float* a = acc[fm][f];
                    stg[nl * 132 + mr]           = a[0];
                    stg[(nl + 1) * 132 + mr]     = a[1];
                    stg[nl * 132 + mr + 8]       = a[2];
                    stg[(nl + 1) * 132 + mr + 8] = a[3];
                }
        }
        __syncthreads();
#pragma unroll
        for (int r = 0; r < 24; r++) {
            int flat = tid + r * NT;
            int mm = flat & 127, nn = flat >> 7;
            Outp[(ocb + h * 96 + nn) * (size_t)HW + p0 + mm] = stg[nn * 132 + mm];
        }
        __syncthreads();
    }
}

// ---------------- init ----------------
__global__ void k_init() {
    int i = blockIdx.x * blockDim.x + threadIdx.x;
    if (i < BB * CC) { g_ssq[i] = 0.f; g_ssk[i] = 0.f; g_sscn[i] = 0.f; g_dot[i] = 0.f; }
    int n2 = BB * NH * CH * CH;
    for (int j = i; j < n2; j += gridDim.x * blockDim.x) { g_S1[j] = 0.f; g_S2[j] = 0.f; }
}

// ---------------- compose cn weights -> bf16 hi/lo [tap][oc][ic] ----------------
__global__ void k_compose(const float* __restrict__ w1, const float* __restrict__ w3) {
    int o = blockIdx.x / 9;
    int t = blockIdx.x % 9;
    int i = threadIdx.x;
    float acc = 0.f;
    for (int m = 0; m < CC; m++)
        acc = fmaf(w3[(o * CC + m) * 9 + t], w1[m * CC + i], acc);
    __nv_bfloat16 h = __float2bfloat16(acc);
    __nv_bfloat16 l = __float2bfloat16(acc - __bfloat162float(h));
    size_t e = ((size_t)t * CC + o) * CC + i;
    g_w3t_h[e] = h; g_w3t_l[e] = l;
}

// ---------------- qkv weight prep ----------------
__global__ void k_wprep(const float* __restrict__ qw) {
    int i = blockIdx.x * blockDim.x + threadIdx.x;
    if (i >= C3 * CC) return;
    float v = qw[i];
    __nv_bfloat16 h = __float2bfloat16(v);
    g_wq_h[i] = h;
    g_wq_l[i] = __float2bfloat16(v - __bfloat162float(h));
}

// ================= cn conv 3x3 GEMM (512 thr, double-buffered async B) =================
#define CN_AH 0u
#define CN_PL (3 * 130 * AP)              // 56160 per A plane
#define CN_AL CN_PL
#define CN_B0H (2 * CN_PL)                // 112320
#define CN_B0L (CN_B0H + 192 * AP)        // 139968
#define CN_B1H (CN_B0L + 192 * AP)        // 167616
#define CN_B1L (CN_B1H + 192 * AP)        // 195264
#define CN_SMEM (CN_B1L + 192 * AP)       // 222912

__global__ void __launch_bounds__(NT, 1) k_gemm_cn(const float* __restrict__ cn) {
    extern __shared__ __align__(16) char smem[];
    uint32_t sb = smem_to_u32(smem);
    int tid = threadIdx.x, wid = tid >> 5, lane = tid & 31;
    int b = blockIdx.z, tile = blockIdx.x;
    int mbase = (wid & 3) * 32, nbase = (wid >> 2) * 48;

    float acc[2][6][4];
#pragma unroll
    for (int fm = 0; fm < 2; fm++)
#pragma unroll
        for (int f = 0; f < 6; f++)
#pragma unroll
            for (int r = 0; r < 4; r++) acc[fm][f][r] = 0.f;

    load_b_async(g_w3t_h, g_w3t_l, 0, 0, sb + CN_B0H, sb + CN_B0L, tid);
    CP_COMMIT();

#pragma unroll 1
    for (int kc = 0; kc < 3; kc++) {
        // ---- load A slab: 390 pixel-positions x 64 channels, predicated (SAME pad) ----
        const float* cnb = cn + (size_t)(b * CC + kc * 64) * HW;
#pragma unroll 1
        for (int pp = tid; pp < 390; pp += NT) {
            int yr = pp / 130, xx = pp - yr * 130;
            int gy = tile + yr - 1, gx = xx - 1;
            bool valid = ((unsigned)gy < HH) && ((unsigned)gx < WW);
            const float* src = cnb + (size_t)gy * WW + gx;
            char* aH = smem + CN_AH + (size_t)pp * AP;
            char* aL = smem + CN_AL + (size_t)pp * AP;
#pragma unroll
            for (int k0 = 0; k0 < 64; k0 += 2) {
                float v0 = valid ? src[(size_t)k0 * HW] : 0.f;
                float v1 = valid ? src[(size_t)(k0 + 1) * HW] : 0.f;
                uint32_t hi, lo;
                split_pair(v0, v1, hi, lo);
                *(uint32_t*)(aH + k0 * 2) = hi;
                *(uint32_t*)(aL + k0 * 2) = lo;
            }
        }
#pragma unroll 1
        for (int t9 = 0; t9 < 9; t9++) {
            int c = kc * 9 + t9;
            if (c < 26) {
                int c2 = c + 1;
                int k2 = c2 / 9, t2 = c2 - k2 * 9;
                load_b_async(g_w3t_h, g_w3t_l, (size_t)t2 * CC, k2 * 64,
                             sb + ((c2 & 1) ? CN_B1H : CN_B0H),
                             sb + ((c2 & 1) ? CN_B1L : CN_B0L), tid);
                CP_COMMIT();
                CP_WAIT1();
            } else {
                CP_WAIT0();
            }
            __syncthreads();
            int dyi = t9 / 3, dxi = t9 % 3;
            uint32_t view = (uint32_t)((dyi * 130 + dxi) * AP);
            mma_chunk(sb, CN_AH + view, CN_AL + view, AP,
                      (c & 1) ? CN_B1H : CN_B0H, (c & 1) ? CN_B1L : CN_B0L,
                      lane, mbase, nbase, acc);
            __syncthreads();
        }
    }
    epilogue_store(acc, smem, 0, g_cnf, (size_t)b * CC, tile * 128, tid, wid, lane);
}

// ================= qkv 1x1 GEMM (512 thr, A persistent, async B) =================
#define Q_AH 0u
#define Q_PL (128 * APK)                  // 51200 per A plane
#define Q_AL Q_PL
#define Q_B0H (2 * Q_PL)                  // 102400
#define Q_B0L (Q_B0H + 192 * AP)          // 130048
#define Q_B1H (Q_B0L + 192 * AP)          // 157696
#define Q_B1L (Q_B1H + 192 * AP)          // 185344
#define Q_SMEM (Q_B1L + 192 * AP)         // 212992

__global__ void __launch_bounds__(NT, 1) k_gemm_qkv(const float* __restrict__ x) {
    extern __shared__ __align__(16) char smem[];
    uint32_t sb = smem_to_u32(smem);
    int tid = threadIdx.x, wid = tid >> 5, lane = tid & 31;
    int b = blockIdx.z, tile = blockIdx.x;
    int p0 = tile * 128;
    int mbase = (wid & 3) * 32, nbase = (wid >> 2) * 48;

    load_b_async(g_wq_h, g_wq_l, 0, 0, sb + Q_B0H, sb + Q_B0L, tid);
    CP_COMMIT();

    // ---- load full-K A panel once: [128 px][192 k] hi/lo ----
    {
        int m = tid & 127, g = tid >> 7;   // g in 0..3
        const float* a0 = x + (size_t)(b * CC) * HW + p0 + m;
        char* aH = smem + Q_AH + (size_t)m * APK;
        char* aL = smem + Q_AL + (size_t)m * APK;
#pragma unroll
        for (int i = 0; i < 24; i++) {
            int k0 = g * 48 + i * 2;
            float v0 = a0[(size_t)k0 * HW];
            float v1 = a0[(size_t)(k0 + 1) * HW];
            uint32_t hi, lo;
            split_pair(v0, v1, hi, lo);
            *(uint32_t*)(aH + k0 * 2) = hi;
            *(uint32_t*)(aL + k0 * 2) = lo;
        }
    }

#pragma unroll 1
    for (int grp = 0; grp < 3; grp++) {
        float acc[2][6][4];
#pragma unroll
        for (int fm = 0; fm < 2; fm++)
#pragma unroll
            for (int f = 0; f < 6; f++)
#pragma unroll
                for (int r = 0; r < 4; r++) acc[fm][f][r] = 0.f;

#pragma unroll 1
        for (int kc = 0; kc < 3; kc++) {
            int c = grp * 3 + kc;
            if (c < 8) {
                int c2 = c + 1;
                int g2 = c2 / 3, k2 = c2 - g2 * 3;
                load_b_async(g_wq_h, g_wq_l, (size_t)g2 * CC, k2 * 64,
                             sb + ((c2 & 1) ? Q_B1H : Q_B0H),
                             sb + ((c2 & 1) ? Q_B1L : Q_B0L), tid);
                CP_COMMIT();
                CP_WAIT1();
            } else {
                CP_WAIT0();
            }
            __syncthreads();
            mma_chunk(sb, Q_AH + (uint32_t)(kc * 128), Q_AL + (uint32_t)(kc * 128), APK,
                      (c & 1) ? Q_B1H : Q_B0H, (c & 1) ? Q_B1L : Q_B0L,
                      lane, mbase, nbase, acc);
            __syncthreads();
        }
        // stage in the JUST-CONSUMED buffer pair (c=grp*3+2); the pending
        // cross-group prefetch lives in the OTHER pair. (R15 bug: fixed buf0
        // collided with the grp1->grp2 prefetch into buf0.)
        uint32_t stgOff = (((grp * 3 + 2) & 1) ? Q_B1H : Q_B0H);
        epilogue_store(acc, smem, stgOff, g_mid, (size_t)b * C3 + grp * CC, p0, tid, wid, lane);
    }
}

// ================= final 1x1 GEMM (512 thr, Wcomb @ v, async B) =================
#define F_AH 0u
#define F_AL (128 * AP)                   // 18432
#define F_B0H (2 * 128 * AP)              // 36864
#define F_B0L (F_B0H + 192 * AP)          // 64512
#define F_B1H (F_B0L + 192 * AP)          // 92160
#define F_B1L (F_B1H + 192 * AP)          // 119808
#define F_SMEM (F_B1L + 192 * AP)         // 147456

__global__ void __launch_bounds__(NT, 1) k_gemm_fin(float* __restrict__ OutExt) {
    extern __shared__ __align__(16) char smem[];
    uint32_t sb = smem_to_u32(smem);
    int tid = threadIdx.x, wid = tid >> 5, lane = tid & 31;
    int b = blockIdx.z, tile = blockIdx.x;
    int p0 = tile * 128;
    int mbase = (wid & 3) * 32, nbase = (wid >> 2) * 48;

    float acc[2][6][4];
#pragma unroll
    for (int fm = 0; fm < 2; fm++)
#pragma unroll
        for (int f = 0; f < 6; f++)
#pragma unroll
            for (int r = 0; r < 4; r++) acc[fm][f][r] = 0.f;

    load_b_async(g_wcb_h, g_wcb_l, (size_t)b * CC, 0, sb + F_B0H, sb + F_B0L, tid);
    CP_COMMIT();

#pragma unroll 1
    for (int kc = 0; kc < 3; kc++) {
        if (kc < 2) {
            load_b_async(g_wcb_h, g_wcb_l, (size_t)b * CC, (kc + 1) * 64,
                         sb + (((kc + 1) & 1) ? F_B1H : F_B0H),
                         sb + (((kc + 1) & 1) ? F_B1L : F_B0L), tid);
            CP_COMMIT();
        }
        // ---- A tile: v channels [128 px][64 k] ----
        {
            int m = tid & 127, g = tid >> 7;
            const float* a0 = g_qkv + (size_t)(b * C3 + 2 * CC + kc * 64) * HW + p0 + m;
            char* aH = smem + F_AH + (size_t)m * AP;
            char* aL = smem + F_AL + (size_t)m * AP;
#pragma unroll
            for (int i = 0; i < 8; i++) {
                int k0 = g * 16 + i * 2;
                float v0 = a0[(size_t)k0 * HW];
                float v1 = a0[(size_t)(k0 + 1) * HW];
                uint32_t hi, lo;
                split_pair(v0, v1, hi, lo);
                *(uint32_t*)(aH + k0 * 2) = hi;
                *(uint32_t*)(aL + k0 * 2) = lo;
            }
        }
        if (kc < 2) { CP_WAIT1(); } else { CP_WAIT0(); }
        __syncthreads();
        mma_chunk(sb, F_AH, F_AL, AP,
                  (kc & 1) ? F_B1H : F_B0H, (kc & 1) ? F_B1L : F_B0L,
                  lane, mbase, nbase, acc);
        __syncthreads();
    }
    epilogue_store(acc, smem, 0, OutExt, (size_t)b * CC, p0, tid, wid, lane);
}

// ---------------- depthwise 3x3 (+ sumsq q/k/cn, dot(q,cn_f)) ----------------
__global__ void __launch_bounds__(256) k_dw(const float* __restrict__ dww) {
    __shared__ float sT[10][130];
    int y0 = blockIdx.x * 8;
    int oc = blockIdx.y;
    int b  = blockIdx.z;
    int tid = threadIdx.x;

    const float* mid = g_mid + (size_t)(b * C3 + oc) * HW;
    for (int idx = tid; idx < 10 * 130; idx += 256) {
        int r = idx / 130, cc = idx % 130;
        int y = y0 + r - 1, x = cc - 1;
        sT[r][cc] = ((unsigned)y < HH && (unsigned)x < WW) ? mid[y * WW + x] : 0.f;
    }
    float dw[9];
#pragma unroll
    for (int t = 0; t < 9; t++) dw[t] = dww[oc * 9 + t];
    __syncthreads();

    int py = tid >> 5, lane = tid & 31, xb = lane * 4;
    float out4[4];
#pragma unroll
    for (int j = 0; j < 4; j++) {
        float v = 0.f;
#pragma unroll
        for (int ky = 0; ky < 3; ky++)
#pragma unroll
            for (int kx = 0; kx < 3; kx++)
                v = fmaf(dw[ky * 3 + kx], sT[py + ky][xb + j + kx], v);
        out4[j] = v;
    }
    size_t base = (size_t)(b * C3 + oc) * HW + (y0 + py) * WW + xb;
#pragma unroll
    for (int j = 0; j < 4; j++) g_qkv[base + j] = out4[j];

    if (oc < 2 * CC) {
        float ss = 0.f, dd = 0.f, sc = 0.f;
#pragma unroll
        for (int j = 0; j < 4; j++) ss = fmaf(out4[j], out4[j], ss);
        if (oc < CC) {
            const float* cf = g_cnf + (size_t)(b * CC + oc) * HW + (y0 + py) * WW + xb;
#pragma unroll
            for (int j = 0; j < 4; j++) {
                float cv = cf[j];
                dd = fmaf(out4[j], cv, dd);
                sc = fmaf(cv, cv, sc);
            }
        }
        for (int off = 16; off; off >>= 1) {
            ss += __shfl_xor_sync(0xffffffffu, ss, off);
            dd += __shfl_xor_sync(0xffffffffu, dd, off);
            sc += __shfl_xor_sync(0xffffffffu, sc, off);
        }
        if (lane == 0) {
            if (oc < CC) {
                atomicAdd(&g_ssq[b * CC + oc], ss);
                atomicAdd(&g_dot[b * CC + oc], dd);
                atomicAdd(&g_sscn[b * CC + oc], sc);
            } else {
                atomicAdd(&g_ssk[b * CC + oc - CC], ss);
            }
        }
    }
}

// ---------------- attention GEMMs: S1 = q k^T, S2 = cn k^T ----------------
__global__ void __launch_bounds__(256) k_attn_gemm() {
    __shared__ float sQ[48][33], sK[48][33], sC[48][33];
    int b = blockIdx.z, h = blockIdx.y;
    int s0 = blockIdx.x * 1024;
    int tid = threadIdx.x;
    int ti = tid >> 4, tj = tid & 15;

    float a1[3][3] = {}, a2[3][3] = {};
    const float* qb = g_qkv + (size_t)(b * C3 + h * CH) * HW;
    const float* kb = g_qkv + (size_t)(b * C3 + CC + h * CH) * HW;
    const float* cb = g_cnf + (size_t)(b * CC + h * CH) * HW;

    for (int st = 0; st < 1024; st += 32) {
#pragma unroll
        for (int i = 0; i < 6; i++) {
            int idx = tid + i * 256;
            int r = idx >> 5, ss = idx & 31;
            sQ[r][ss] = qb[(size_t)r * HW + s0 + st + ss];
            sK[r][ss] = kb[(size_t)r * HW + s0 + st + ss];
            sC[r][ss] = cb[(size_t)r * HW + s0 + st + ss];
        }
        __syncthreads();
#pragma unroll 4
        for (int ss = 0; ss < 32; ss++) {
            float qv[3], kv[3], cv[3];
#pragma unroll
            for (int i = 0; i < 3; i++) {
                qv[i] = sQ[ti * 3 + i][ss];
                cv[i] = sC[ti * 3 + i][ss];
                kv[i] = sK[tj * 3 + i][ss];
            }
#pragma unroll
            for (int i = 0; i < 3; i++)
#pragma unroll
                for (int j = 0; j < 3; j++) {
                    a1[i][j] = fmaf(qv[i], kv[j], a1[i][j]);
                    a2[i][j] = fmaf(cv[i], kv[j], a2[i][j]);
                }
        }
        __syncthreads();
    }
    int base = ((b * NH + h) * CH) * CH;
#pragma unroll
    for (int i = 0; i < 3; i++)
#pragma unroll
        for (int j = 0; j < 3; j++) {
            atomicAdd(&g_S1[base + (ti * 3 + i) * CH + tj * 3 + j], a1[i][j]);
            atomicAdd(&g_S2[base + (ti * 3 + i) * CH + tj * 3 + j], a2[i][j]);
        }
}

// ---------------- finalize: normalize, softmax, Wcomb(hi/lo bf16) ----------------
__global__ void __launch_bounds__(256) k_finalize(const float* __restrict__ proj_w,
                                                  const float* __restrict__ temp) {
    __shared__ float L[CH * CH];
    __shared__ float rfA[CH], rfB[CH], cfc[CH];
    __shared__ float sWp[CC * CH];

    int h = blockIdx.x, b = blockIdx.y;
    int tid = threadIdx.x;

    if (tid < CH) {
        int gi = b * CC + h * CH + tid;
        float ssq = g_ssq[gi], sscn = g_sscn[gi], dt = g_dot[gi], ssk = g_ssk[gi];
        float a  = 1.f / fmaxf(sqrtf(ssq), EPSN);
        float bf = 1.f / fmaxf(sqrtf(sscn), EPSN);
        float ssum = ssq * a * a + sscn * bf * bf + 2.f * dt * a * bf;
        float inv_ns = 1.f / fmaxf(sqrtf(fmaxf(ssum, 0.f)), EPSN);
        rfA[tid] = a * inv_ns;
        rfB[tid] = bf * inv_ns;
        cfc[tid] = 1.f / fmaxf(sqrtf(ssk), EPSN);
    }
    __syncthreads();

    float tv = temp[h];
    int base = ((b * NH + h) * CH) * CH;
    for (int e = tid; e < CH * CH; e += 256) {
        int c = e / CH, d = e % CH;
        L[e] = (g_S1[base + e] * rfA[c] + g_S2[base + e] * rfB[c]) * cfc[d] * tv;
    }
    __syncthreads();

    int w = tid >> 5, lane = tid & 31;
    for (int k = 0; k < 6; k++) {
        int r = w * 6 + k;
        float v0 = L[r * CH + lane];
        float v1 = (lane < 16) ? L[r * CH + 32 + lane] : -1e30f;
        float m = fmaxf(v0, v1);
        for (int off = 16; off; off >>= 1) m = fmaxf(m, __shfl_xor_sync(0xffffffffu, m, off));
        float e0 = expf(v0 - m);
        float e1 = (lane < 16) ? expf(v1 - m) : 0.f;
        float s = e0 + e1;
        for (int off = 16; off; off >>= 1) s += __shfl_xor_sync(0xffffffffu, s, off);
        float inv = 1.f / s;
        L[r * CH + lane] = e0 * inv;
        if (lane < 16) L[r * CH + 32 + lane] = e1 * inv;
    }
    __syncthreads();

    for (int idx = tid; idx < CC * CH; idx += 256)
        sWp[idx] = proj_w[(idx / CH) * CC + h * CH + (idx % CH)];
    __syncthreads();
    for (int e = tid; e < CC * CH; e += 256) {
        int oc = e / CH, d = e % CH;
        float s = 0.f;
#pragma unroll 8
        for (int c = 0; c < CH; c++)
            s = fmaf(sWp[oc * CH + c], L[c * CH + d], s);
        size_t oe = ((size_t)b * CC + oc) * CC + h * CH + d;
        __nv_bfloat16 hv = __float2bfloat16(s);
        g_wcb_h[oe] = hv;
        g_wcb_l[oe] = __float2bfloat16(s - __bfloat162float(hv));
    }
}

// ---------------- launch ----------------
extern "C" void kernel_launch(void* const* d_in, const int* in_sizes, int n_in,
                              void* d_out, int out_size) {
    const float* x    = (const float*)d_in[0];
    const float* cn   = (const float*)d_in[1];
    const float* w1   = (const float*)d_in[2];
    const float* w3   = (const float*)d_in[3];
    const float* qw   = (const float*)d_in[4];
    const float* dww  = (const float*)d_in[5];
    const float* pw   = (const float*)d_in[6];
    const float* temp = (const float*)d_in[7];
    float* out = (float*)d_out;

    cudaFuncSetAttribute(k_gemm_cn,  cudaFuncAttributeMaxDynamicSharedMemorySize, CN_SMEM);
    cudaFuncSetAttribute(k_gemm_qkv, cudaFuncAttributeMaxDynamicSharedMemorySize, Q_SMEM);
    cudaFuncSetAttribute(k_gemm_fin, cudaFuncAttributeMaxDynamicSharedMemorySize, F_SMEM);

    k_init<<<288, 256>>>();
    k_compose<<<CC * 9, CC>>>(w1, w3);
    k_wprep<<<(C3 * CC + 255) / 256, 256>>>(qw);
    k_gemm_cn<<<dim3(128, 1, BB), NT, CN_SMEM>>>(cn);
    k_gemm_qkv<<<dim3(128, 1, BB), NT, Q_SMEM>>>(x);
    k_dw<<<dim3(HH / 8, C3, BB), 256>>>(dww);
    k_attn_gemm<<<dim3(HW / 1024, NH, BB), 256>>>();
    k_finalize<<<dim3(NH, BB), 256>>>(pw, temp);
    k_gemm_fin<<<dim3(128, 1, BB), NT, F_SMEM>>>(out);
}